// round 1
// baseline (speedup 1.0000x reference)
#include <cuda_runtime.h>
#include <math.h>

#define Bx 8
#define Tt 12
#define NN 10000
#define EE 160000
#define OD 64
#define TILE 16
#define NTILES (NN / TILE) /* 625 */

// ---------------- scratch (__device__ globals; no allocation) ----------------
__device__ float g_xT[Bx * NN * 16];    // x transposed to [b][n][16] (12 used)
__device__ float g_aggX[Bx * NN * 16];  // agg of x over normal edges
__device__ float g_aggC[Bx * NN * 16];  // agg of x over causal edges
__device__ int g_rowN[NN + 1];
__device__ int g_rowC[NN + 1];
__device__ int g_colN[EE];
__device__ int g_colC[EE];
__device__ int g_degN[NN];
__device__ int g_degC[NN];
__device__ int g_curN[NN];
__device__ int g_curC[NN];
// combined 12x64 weights, stored [d][t] for per-thread register preload
__device__ float g_Ph1[OD * Tt], g_Ph2[OD * Tt];
__device__ float g_Pl1[OD * Tt], g_Pl2[OD * Tt], g_Pl3[OD * Tt];
__device__ float g_Pg[OD * Tt];
__device__ float g_bH0[OD], g_bHm[OD], g_bL0[OD], g_bLm[OD], g_bLc[OD];

// ---------------- kernels ----------------

__global__ void zero_kernel() {
    int i = blockIdx.x * blockDim.x + threadIdx.x;
    if (i < NN) {
        g_degN[i] = 0;
        g_degC[i] = 0;
        g_curN[i] = 0;
        g_curC[i] = 0;
    }
}

// Fold all 64x64 projections through W_ht / W_lt into 12x64 matrices.
__global__ void prep_kernel(const float* __restrict__ W_ht, const float* __restrict__ b_ht,
                            const float* __restrict__ W_lt, const float* __restrict__ b_lt,
                            const float* __restrict__ Ws_h, const float* __restrict__ Wn_h,
                            const float* __restrict__ b_h, const float* __restrict__ Ws_l,
                            const float* __restrict__ Wn_l, const float* __restrict__ Wc_l,
                            const float* __restrict__ b_l, const float* __restrict__ Whr,
                            const float* __restrict__ bhr, const float* __restrict__ Wlr,
                            const float* __restrict__ blr, const float* __restrict__ Wg) {
    int d = threadIdx.x;  // 0..63
#pragma unroll 1
    for (int t = 0; t < Tt; t++) {
        float s1 = 0.f, s2 = 0.f, s3 = 0.f, s4 = 0.f, s5 = 0.f;
        for (int k = 0; k < 64; k++) {
            float wht = W_ht[t * 64 + k];
            float wlt = W_lt[t * 64 + k];
            s1 += wht * (Ws_h[k * 64 + d] + 0.2f * Whr[k * 64 + d]);
            s2 += wht * Wn_h[k * 64 + d];
            s3 += wlt * (Ws_l[k * 64 + d] + 0.2f * Wlr[k * 64 + d]);
            s4 += wlt * Wn_l[k * 64 + d];
            s5 += wlt * Wc_l[k * 64 + d];
        }
        g_Ph1[d * Tt + t] = s1;
        g_Ph2[d * Tt + t] = s2;
        g_Pl1[d * Tt + t] = s3;
        g_Pl2[d * Tt + t] = s4;
        g_Pl3[d * Tt + t] = s5;
        g_Pg[d * Tt + t] = 2.0f * Wg[t * 64 + d];  // x_for_residual = 2x
    }
    float bh0 = b_h[d] + 0.2f * bhr[d];
    float bhm = 0.f;
    float bl0 = b_l[d] + 0.2f * blr[d];
    float blm = 0.f, blc = 0.f;
    for (int k = 0; k < 64; k++) {
        bh0 += b_ht[k] * (Ws_h[k * 64 + d] + 0.2f * Whr[k * 64 + d]);
        bhm += b_ht[k] * Wn_h[k * 64 + d];
        bl0 += b_lt[k] * (Ws_l[k * 64 + d] + 0.2f * Wlr[k * 64 + d]);
        blm += b_lt[k] * Wn_l[k * 64 + d];
        blc += b_lt[k] * Wc_l[k * 64 + d];
    }
    g_bH0[d] = bh0;
    g_bHm[d] = bhm;
    g_bL0[d] = bl0;
    g_bLm[d] = blm;
    g_bLc[d] = blc;
}

// x (B,T,N) -> xT (B,N,16) padded, for contiguous per-node gathers.
__global__ void transpose_kernel(const float* __restrict__ x) {
    int idx = blockIdx.x * blockDim.x + threadIdx.x;
    if (idx >= Bx * NN) return;
    int b = idx / NN;
    int n = idx - b * NN;
    float v[16];
#pragma unroll
    for (int t = 0; t < Tt; t++) v[t] = x[((size_t)b * Tt + t) * NN + n];
    v[12] = v[13] = v[14] = v[15] = 0.f;
    float4* dst = (float4*)(g_xT + (size_t)idx * 16);
    dst[0] = make_float4(v[0], v[1], v[2], v[3]);
    dst[1] = make_float4(v[4], v[5], v[6], v[7]);
    dst[2] = make_float4(v[8], v[9], v[10], v[11]);
    dst[3] = make_float4(v[12], v[13], v[14], v[15]);
}

__global__ void count_kernel(const int* __restrict__ ei, const int* __restrict__ cei) {
    int i = blockIdx.x * blockDim.x + threadIdx.x;
    if (i >= 2 * EE) return;
    if (i < EE) {
        atomicAdd(&g_degN[ei[EE + i]], 1);  // dst row
    } else {
        atomicAdd(&g_degC[cei[EE + (i - EE)]], 1);
    }
}

// Single-block exclusive scan per edge set (blockIdx.x selects set).
__global__ void scan_kernel() {
    const int* deg = (blockIdx.x == 0) ? g_degN : g_degC;
    int* row = (blockIdx.x == 0) ? g_rowN : g_rowC;
    __shared__ int sm[1024];
    const int CH = 10;  // 1024*10 >= 10000
    int t = threadIdx.x;
    int loc[CH];
    int run = 0;
#pragma unroll
    for (int j = 0; j < CH; j++) {
        int i = t * CH + j;
        int v = (i < NN) ? deg[i] : 0;
        run += v;
        loc[j] = run;
    }
    sm[t] = run;
    __syncthreads();
    for (int off = 1; off < 1024; off <<= 1) {
        int v = (t >= off) ? sm[t - off] : 0;
        __syncthreads();
        sm[t] += v;
        __syncthreads();
    }
    int base = sm[t] - run;  // exclusive prefix for this thread's chunk
#pragma unroll
    for (int j = 0; j < CH; j++) {
        int i = t * CH + j;
        if (i < NN) row[i + 1] = base + loc[j];
    }
    if (t == 0) row[0] = 0;
}

__global__ void fill_kernel(const int* __restrict__ ei, const int* __restrict__ cei) {
    int i = blockIdx.x * blockDim.x + threadIdx.x;
    if (i >= 2 * EE) return;
    if (i < EE) {
        int dd = ei[EE + i];
        int p = atomicAdd(&g_curN[dd], 1);
        g_colN[g_rowN[dd] + p] = ei[i];
    } else {
        i -= EE;
        int dd = cei[EE + i];
        int p = atomicAdd(&g_curC[dd], 1);
        g_colC[g_rowC[dd] + p] = cei[i];
    }
}

// Gather-aggregate raw x (12-dim) per (node, t), all 8 batches per thread.
__global__ void agg_kernel() {
    int idx = blockIdx.x * blockDim.x + threadIdx.x;
    if (idx >= NN * 16) return;
    int t = idx & 15;
    int n = idx >> 4;
    if (t >= Tt) return;
    {
        int rs = g_rowN[n], re = g_rowN[n + 1];
        float acc[Bx];
#pragma unroll
        for (int b = 0; b < Bx; b++) acc[b] = 0.f;
        for (int e = rs; e < re; e++) {
            int c = g_colN[e];
            const float* p = g_xT + c * 16 + t;
#pragma unroll
            for (int b = 0; b < Bx; b++) acc[b] += p[b * NN * 16];
        }
        float invd = 1.0f / fmaxf((float)(re - rs), 1.0f);
#pragma unroll
        for (int b = 0; b < Bx; b++) g_aggX[b * NN * 16 + n * 16 + t] = acc[b] * invd;
    }
    {
        int rs = g_rowC[n], re = g_rowC[n + 1];
        float acc[Bx];
#pragma unroll
        for (int b = 0; b < Bx; b++) acc[b] = 0.f;
        for (int e = rs; e < re; e++) {
            int c = g_colC[e];
            const float* p = g_xT + c * 16 + t;
#pragma unroll
            for (int b = 0; b < Bx; b++) acc[b] += p[b * NN * 16];
        }
        float invd = 1.0f / fmaxf((float)(re - rs), 1.0f);
#pragma unroll
        for (int b = 0; b < Bx; b++) g_aggC[b * NN * 16 + n * 16 + t] = acc[b] * invd;
    }
}

// Fused epilogue: per-node 12->64 GEMVs (weights in registers), 3x LayerNorm,
// leaky-relu / gelu / softmax gate, transposed coalesced output.
__global__ void __launch_bounds__(256, 2) final_kernel(
    float* __restrict__ out, const float* __restrict__ bg, const float* __restrict__ ghn_,
    const float* __restrict__ bhn_, const float* __restrict__ gln_, const float* __restrict__ bln_,
    const float* __restrict__ ggn_, const float* __restrict__ bgn_, const float* __restrict__ Wa,
    const float* __restrict__ ba) {
    int tid = threadIdx.x;
    int d = tid & 63;
    int grp = tid >> 6;        // 4 node-groups per block
    int w = (tid >> 5) & 1;    // warp within group

    float ph1[Tt], ph2[Tt], pl1[Tt], pl2[Tt], pl3[Tt], pg[Tt];
#pragma unroll
    for (int t = 0; t < Tt; t++) {
        ph1[t] = g_Ph1[d * Tt + t];
        ph2[t] = g_Ph2[d * Tt + t];
        pl1[t] = g_Pl1[d * Tt + t];
        pl2[t] = g_Pl2[d * Tt + t];
        pl3[t] = g_Pl3[d * Tt + t];
        pg[t] = g_Pg[d * Tt + t];
    }
    float bH0 = g_bH0[d], bHm = g_bHm[d], bL0 = g_bL0[d], bLm = g_bLm[d], bLc = g_bLc[d];
    float bgd = bg[d];
    float ghn = ghn_[d], bhn = bhn_[d], gln = gln_[d], bln = bln_[d], ggn = ggn_[d], bgn = bgn_[d];
    float waH0 = Wa[d * 2 + 0], waH1 = Wa[d * 2 + 1];
    float waL0 = Wa[(64 + d) * 2 + 0], waL1 = Wa[(64 + d) * 2 + 1];
    float ba0 = ba[0], ba1 = ba[1];

    __shared__ float featX[4][16], featA[4][16], featC[4][16];
    __shared__ float degs[4][2];
    __shared__ float red1[4][2][6];
    __shared__ float red2[4][2][2];
    __shared__ float outs[3][64][17];  // pad 17 -> conflict-free

    int ntot = Bx * NTILES;
    for (int tile = blockIdx.x; tile < ntot; tile += gridDim.x) {
        int b = tile / NTILES;
        int n0 = (tile - b * NTILES) * TILE;
#pragma unroll 1
        for (int pass = 0; pass < 4; pass++) {
            int j = pass * 4 + grp;
            int n = n0 + j;
            __syncthreads();
            int base = (b * NN + n) * 16;
            if (d < 16)
                featX[grp][d] = g_xT[base + d];
            else if (d < 32)
                featA[grp][d - 16] = g_aggX[base + d - 16];
            else if (d < 48)
                featC[grp][d - 32] = g_aggC[base + d - 32];
            else if (d == 48)
                degs[grp][0] = (g_rowN[n + 1] > g_rowN[n]) ? 1.f : 0.f;
            else if (d == 49)
                degs[grp][1] = (g_rowC[n + 1] > g_rowC[n]) ? 1.f : 0.f;
            __syncthreads();

            float m = degs[grp][0], mc = degs[grp][1];
            float hp = bH0 + m * bHm;
            float lp = bL0 + m * bLm + mc * bLc;
            float rp = bgd;
#pragma unroll
            for (int t = 0; t < Tt; t++) {
                float fx = featX[grp][t], fa = featA[grp][t], fc = featC[grp][t];
                hp = fmaf(fx, ph1[t], hp);
                hp = fmaf(fa, ph2[t], hp);
                lp = fmaf(fx, pl1[t], lp);
                lp = fmaf(fa, pl2[t], lp);
                lp = fmaf(fc, pl3[t], lp);
                rp = fmaf(fx, pg[t], rp);
            }
            float s[6] = {hp, hp * hp, lp, lp * lp, rp, rp * rp};
#pragma unroll
            for (int o = 16; o > 0; o >>= 1) {
#pragma unroll
                for (int i = 0; i < 6; i++) s[i] += __shfl_xor_sync(0xffffffffu, s[i], o);
            }
            if ((tid & 31) == 0) {
#pragma unroll
                for (int i = 0; i < 6; i++) red1[grp][w][i] = s[i];
            }
            __syncthreads();
            float tot[6];
#pragma unroll
            for (int i = 0; i < 6; i++) tot[i] = red1[grp][0][i] + red1[grp][1][i];
            const float inv = 1.0f / 64.0f;
            float mh = tot[0] * inv, vh = tot[1] * inv - mh * mh;
            float ml = tot[2] * inv, vl = tot[3] * inv - ml * ml;
            float mr = tot[4] * inv, vr = tot[5] * inv - mr * mr;
            float high = (hp - mh) * rsqrtf(vh + 1e-5f) * ghn + bhn;
            high = (high >= 0.f) ? high : 0.1f * high;
            float lowv = (lp - ml) * rsqrtf(vl + 1e-5f) * gln + bln;
            lowv = 0.5f * lowv * (1.0f + erff(lowv * 0.70710678118654752f));
            float res = (rp - mr) * rsqrtf(vr + 1e-5f) * ggn + bgn;

            float v0 = high * waH0 + lowv * waL0;
            float v1 = high * waH1 + lowv * waL1;
#pragma unroll
            for (int o = 16; o > 0; o >>= 1) {
                v0 += __shfl_xor_sync(0xffffffffu, v0, o);
                v1 += __shfl_xor_sync(0xffffffffu, v1, o);
            }
            if ((tid & 31) == 0) {
                red2[grp][w][0] = v0;
                red2[grp][w][1] = v1;
            }
            __syncthreads();
            float l0 = red2[grp][0][0] + red2[grp][1][0] + ba0;
            float l1 = red2[grp][0][1] + red2[grp][1][1] + ba1;
            float a0 = 1.0f / (1.0f + expf(l1 - l0));
            float a1 = 1.0f - a0;
            float fused = a0 * high + a1 * lowv + 0.3f * (high + lowv) + 0.1f * res;
            outs[0][d][j] = fused;
            outs[1][d][j] = high;
            outs[2][d][j] = lowv;
        }
        __syncthreads();
#pragma unroll
        for (int it = 0; it < 12; it++) {
            int idx = it * 256 + tid;
            int jj = idx & 15;
            int dd = (idx >> 4) & 63;
            int a = idx >> 10;
            out[(size_t)a * (Bx * OD * NN) + ((size_t)(b * OD + dd)) * NN + n0 + jj] =
                outs[a][dd][jj];
        }
    }
}

// ---------------- launch ----------------

extern "C" void kernel_launch(void* const* d_in, const int* in_sizes, int n_in, void* d_out,
                              int out_size) {
    const float* x = (const float*)d_in[0];
    const int* ei = (const int*)d_in[1];
    const int* cei = (const int*)d_in[2];
    const float* W_ht = (const float*)d_in[3];
    const float* b_ht = (const float*)d_in[4];
    const float* W_lt = (const float*)d_in[5];
    const float* b_lt = (const float*)d_in[6];
    const float* Ws_h = (const float*)d_in[7];
    const float* Wn_h = (const float*)d_in[8];
    const float* b_h = (const float*)d_in[9];
    const float* Ws_l = (const float*)d_in[10];
    const float* Wn_l = (const float*)d_in[11];
    const float* Wc_l = (const float*)d_in[12];
    const float* b_l = (const float*)d_in[13];
    const float* Whr = (const float*)d_in[14];
    const float* bhr = (const float*)d_in[15];
    const float* Wlr = (const float*)d_in[16];
    const float* blr = (const float*)d_in[17];
    const float* ghn = (const float*)d_in[18];
    const float* bhn = (const float*)d_in[19];
    const float* gln = (const float*)d_in[20];
    const float* bln = (const float*)d_in[21];
    const float* Wa = (const float*)d_in[22];
    const float* ba = (const float*)d_in[23];
    const float* Wg = (const float*)d_in[24];
    const float* bg = (const float*)d_in[25];
    const float* ggn = (const float*)d_in[26];
    const float* bgn = (const float*)d_in[27];
    float* out = (float*)d_out;

    zero_kernel<<<(NN + 255) / 256, 256>>>();
    prep_kernel<<<1, 64>>>(W_ht, b_ht, W_lt, b_lt, Ws_h, Wn_h, b_h, Ws_l, Wn_l, Wc_l, b_l, Whr,
                           bhr, Wlr, blr, Wg);
    transpose_kernel<<<(Bx * NN + 255) / 256, 256>>>(x);
    count_kernel<<<(2 * EE + 255) / 256, 256>>>(ei, cei);
    scan_kernel<<<2, 1024>>>();
    fill_kernel<<<(2 * EE + 255) / 256, 256>>>(ei, cei);
    agg_kernel<<<(NN * 16 + 255) / 256, 256>>>();
    final_kernel<<<1184, 256>>>(out, bg, ghn, bhn, gln, bln, ggn, bgn, Wa, ba);
}

// round 2
// speedup vs baseline: 1.2586x; 1.2586x over previous
#include <cuda_runtime.h>
#include <math.h>

#define Bx 8
#define Tt 12
#define NN 10000
#define EE 160000
#define OD 64
#define TILE 16
#define NTILES (NN / TILE) /* 625 */

// ---------------- scratch (__device__ globals; no allocation) ----------------
__device__ float g_xT[Bx * NN * 16];    // x transposed to [b][n][16] (12 used)
__device__ float g_aggX[Bx * NN * 16];  // agg of x over normal edges
__device__ float g_aggC[Bx * NN * 16];  // agg of x over causal edges
__device__ int g_rowN[NN + 1];
__device__ int g_rowC[NN + 1];
__device__ int g_colN[EE];
__device__ int g_colC[EE];
__device__ int g_degN[NN];
__device__ int g_degC[NN];
__device__ int g_curN[NN];
__device__ int g_curC[NN];
// combined 12x64 weights, stored [d][t] for per-thread register preload
__device__ float g_Ph1[OD * Tt], g_Ph2[OD * Tt];
__device__ float g_Pl1[OD * Tt], g_Pl2[OD * Tt], g_Pl3[OD * Tt];
__device__ float g_Pg[OD * Tt];
__device__ float g_bH0[OD], g_bHm[OD], g_bL0[OD], g_bLm[OD], g_bLc[OD];

// ---------------- K1: fused zero + transpose + prep ----------------
// blocks [0,313): transpose; [313,353): zero counters; [353,357): prep weights.
#define TR_BLOCKS 313
#define Z_BLOCKS 40

__global__ void init_kernel(const float* __restrict__ x, const float* __restrict__ W_ht,
                            const float* __restrict__ b_ht, const float* __restrict__ W_lt,
                            const float* __restrict__ b_lt, const float* __restrict__ Ws_h,
                            const float* __restrict__ Wn_h, const float* __restrict__ b_h,
                            const float* __restrict__ Ws_l, const float* __restrict__ Wn_l,
                            const float* __restrict__ Wc_l, const float* __restrict__ b_l,
                            const float* __restrict__ Whr, const float* __restrict__ bhr,
                            const float* __restrict__ Wlr, const float* __restrict__ blr,
                            const float* __restrict__ Wg) {
    int bid = blockIdx.x;
    int tid = threadIdx.x;
    if (bid < TR_BLOCKS) {
        int idx = bid * 256 + tid;
        if (idx >= Bx * NN) return;
        int b = idx / NN;
        int n = idx - b * NN;
        float v[16];
#pragma unroll
        for (int t = 0; t < Tt; t++) v[t] = x[((size_t)b * Tt + t) * NN + n];
        v[12] = v[13] = v[14] = v[15] = 0.f;
        float4* dst = (float4*)(g_xT + (size_t)idx * 16);
        dst[0] = make_float4(v[0], v[1], v[2], v[3]);
        dst[1] = make_float4(v[4], v[5], v[6], v[7]);
        dst[2] = make_float4(v[8], v[9], v[10], v[11]);
        dst[3] = make_float4(v[12], v[13], v[14], v[15]);
    } else if (bid < TR_BLOCKS + Z_BLOCKS) {
        int i = (bid - TR_BLOCKS) * 256 + tid;
        if (i < NN) {
            g_degN[i] = 0;
            g_degC[i] = 0;
            g_curN[i] = 0;
            g_curC[i] = 0;
        }
    } else {
        int pid = (bid - TR_BLOCKS - Z_BLOCKS) * 256 + tid;
        if (pid >= 13 * 64) return;
        int t = pid >> 6;
        int d = pid & 63;
        if (t < Tt) {
            float s1 = 0.f, s2 = 0.f, s3 = 0.f, s4 = 0.f, s5 = 0.f;
            for (int k = 0; k < 64; k++) {
                float wht = W_ht[t * 64 + k];
                float wlt = W_lt[t * 64 + k];
                s1 += wht * (Ws_h[k * 64 + d] + 0.2f * Whr[k * 64 + d]);
                s2 += wht * Wn_h[k * 64 + d];
                s3 += wlt * (Ws_l[k * 64 + d] + 0.2f * Wlr[k * 64 + d]);
                s4 += wlt * Wn_l[k * 64 + d];
                s5 += wlt * Wc_l[k * 64 + d];
            }
            g_Ph1[d * Tt + t] = s1;
            g_Ph2[d * Tt + t] = s2;
            g_Pl1[d * Tt + t] = s3;
            g_Pl2[d * Tt + t] = s4;
            g_Pl3[d * Tt + t] = s5;
            g_Pg[d * Tt + t] = 2.0f * Wg[t * 64 + d];  // x_for_residual = 2x
        } else {
            float bh0 = b_h[d] + 0.2f * bhr[d];
            float bhm = 0.f;
            float bl0 = b_l[d] + 0.2f * blr[d];
            float blm = 0.f, blc = 0.f;
            for (int k = 0; k < 64; k++) {
                bh0 += b_ht[k] * (Ws_h[k * 64 + d] + 0.2f * Whr[k * 64 + d]);
                bhm += b_ht[k] * Wn_h[k * 64 + d];
                bl0 += b_lt[k] * (Ws_l[k * 64 + d] + 0.2f * Wlr[k * 64 + d]);
                blm += b_lt[k] * Wn_l[k * 64 + d];
                blc += b_lt[k] * Wc_l[k * 64 + d];
            }
            g_bH0[d] = bh0;
            g_bHm[d] = bhm;
            g_bL0[d] = bl0;
            g_bLm[d] = blm;
            g_bLc[d] = blc;
        }
    }
}

// ---------------- CSR build ----------------

__global__ void count_kernel(const int* __restrict__ ei, const int* __restrict__ cei) {
    int i = blockIdx.x * blockDim.x + threadIdx.x;
    const int half = EE / 4;  // 40000 int4s per dst array
    if (i < half) {
        int4 v = ((const int4*)(ei + EE))[i];
        atomicAdd(&g_degN[v.x], 1);
        atomicAdd(&g_degN[v.y], 1);
        atomicAdd(&g_degN[v.z], 1);
        atomicAdd(&g_degN[v.w], 1);
    } else if (i < 2 * half) {
        int4 v = ((const int4*)(cei + EE))[i - half];
        atomicAdd(&g_degC[v.x], 1);
        atomicAdd(&g_degC[v.y], 1);
        atomicAdd(&g_degC[v.z], 1);
        atomicAdd(&g_degC[v.w], 1);
    }
}

// Single-block exclusive scan per edge set (blockIdx.x selects set).
__global__ void scan_kernel() {
    const int* deg = (blockIdx.x == 0) ? g_degN : g_degC;
    int* row = (blockIdx.x == 0) ? g_rowN : g_rowC;
    __shared__ int sm[1024];
    const int CH = 10;
    int t = threadIdx.x;
    int loc[CH];
    int run = 0;
#pragma unroll
    for (int j = 0; j < CH; j++) {
        int i = t * CH + j;
        int v = (i < NN) ? deg[i] : 0;
        run += v;
        loc[j] = run;
    }
    sm[t] = run;
    __syncthreads();
    for (int off = 1; off < 1024; off <<= 1) {
        int v = (t >= off) ? sm[t - off] : 0;
        __syncthreads();
        sm[t] += v;
        __syncthreads();
    }
    int base = sm[t] - run;
#pragma unroll
    for (int j = 0; j < CH; j++) {
        int i = t * CH + j;
        if (i < NN) row[i + 1] = base + loc[j];
    }
    if (t == 0) row[0] = 0;
}

__global__ void fill_kernel(const int* __restrict__ ei, const int* __restrict__ cei) {
    int i = blockIdx.x * blockDim.x + threadIdx.x;
    if (i >= 2 * EE) return;
    if (i < EE) {
        int dd = __ldg(&ei[EE + i]);
        int p = atomicAdd(&g_curN[dd], 1);
        g_colN[g_rowN[dd] + p] = __ldg(&ei[i]);
    } else {
        i -= EE;
        int dd = __ldg(&cei[EE + i]);
        int p = atomicAdd(&g_curC[dd], 1);
        g_colC[g_rowC[dd] + p] = __ldg(&cei[i]);
    }
}

// ---------------- aggregation ----------------
// Split normal/causal into independent thread ranges for 2x memory parallelism.
__global__ void agg_kernel() {
    int idx = blockIdx.x * blockDim.x + threadIdx.x;
    if (idx >= NN * 32) return;
    int t = idx & 15;
    if (t >= Tt) return;
    int n = idx >> 4;
    int causal = (n >= NN);
    if (causal) n -= NN;
    const int* __restrict__ row = causal ? g_rowC : g_rowN;
    const int* __restrict__ col = causal ? g_colC : g_colN;
    float* __restrict__ dst = causal ? g_aggC : g_aggX;
    int rs = row[n], re = row[n + 1];
    float acc[Bx];
#pragma unroll
    for (int b = 0; b < Bx; b++) acc[b] = 0.f;
#pragma unroll 2
    for (int e = rs; e < re; e++) {
        int c = __ldg(&col[e]);
        const float* p = g_xT + c * 16 + t;
#pragma unroll
        for (int b = 0; b < Bx; b++) acc[b] += __ldg(&p[b * NN * 16]);
    }
    float invd = 1.0f / fmaxf((float)(re - rs), 1.0f);
#pragma unroll
    for (int b = 0; b < Bx; b++) dst[b * NN * 16 + n * 16 + t] = acc[b] * invd;
}

// ---------------- fused epilogue ----------------
// 512 threads = 8 independent 64-thread node-groups. Per-node sync via named
// barriers (bar.sync grp+1, 64) only; block-wide sync only around output stage.
__global__ void __launch_bounds__(512, 1) final_kernel(
    float* __restrict__ out, const float* __restrict__ bg, const float* __restrict__ ghn_,
    const float* __restrict__ bhn_, const float* __restrict__ gln_, const float* __restrict__ bln_,
    const float* __restrict__ ggn_, const float* __restrict__ bgn_, const float* __restrict__ Wa,
    const float* __restrict__ ba) {
    int tid = threadIdx.x;
    int d = tid & 63;
    int grp = tid >> 6;      // 0..7
    int w = (tid >> 5) & 1;  // warp within group
    int lane = tid & 31;

    float ph1[Tt], ph2[Tt], pl1[Tt], pl2[Tt], pl3[Tt], pg[Tt];
#pragma unroll
    for (int t = 0; t < Tt; t++) {
        ph1[t] = g_Ph1[d * Tt + t];
        ph2[t] = g_Ph2[d * Tt + t];
        pl1[t] = g_Pl1[d * Tt + t];
        pl2[t] = g_Pl2[d * Tt + t];
        pl3[t] = g_Pl3[d * Tt + t];
        pg[t] = g_Pg[d * Tt + t];
    }
    float bH0 = g_bH0[d], bHm = g_bHm[d], bL0 = g_bL0[d], bLm = g_bLm[d], bLc = g_bLc[d];
    float bgd = bg[d];
    float ghn = ghn_[d], bhn = bhn_[d], gln = gln_[d], bln = bln_[d], ggn = ggn_[d], bgn = bgn_[d];
    float waH0 = Wa[d * 2 + 0], waH1 = Wa[d * 2 + 1];
    float waL0 = Wa[(64 + d) * 2 + 0], waL1 = Wa[(64 + d) * 2 + 1];
    float ba0 = ba[0], ba1 = ba[1];

    __shared__ float red[8][2][8];
    __shared__ float outs[3][64][17];  // pad 17 -> conflict-free

    int ntot = Bx * NTILES;
    for (int tile = blockIdx.x; tile < ntot; tile += gridDim.x) {
        int b = tile / NTILES;
        int n0 = (tile - b * NTILES) * TILE;
#pragma unroll
        for (int rep = 0; rep < 2; rep++) {
            int j = rep * 8 + grp;
            int n = n0 + j;
            int base = (b * NN + n) * 16;
            // lane-mapped feature load (each warp of the group loads its own copy)
            float v0 = (lane < 12)   ? g_xT[base + lane]
                       : (lane < 24) ? g_aggX[base + lane - 12]
                                     : g_aggC[base + lane - 24];
            float v1 = 0.f;
            if (lane < 4)
                v1 = g_aggC[base + 8 + lane];
            else if (lane == 4)
                v1 = (g_rowN[n + 1] > g_rowN[n]) ? 1.f : 0.f;
            else if (lane == 5)
                v1 = (g_rowC[n + 1] > g_rowC[n]) ? 1.f : 0.f;

            float m = __shfl_sync(0xffffffffu, v1, 4);
            float mc = __shfl_sync(0xffffffffu, v1, 5);
            float hp = bH0 + m * bHm;
            float lp = bL0 + m * bLm + mc * bLc;
            float rp = bgd;
#pragma unroll
            for (int t = 0; t < Tt; t++) {
                float fx = __shfl_sync(0xffffffffu, v0, t);
                float fa = __shfl_sync(0xffffffffu, v0, 12 + t);
                float fc = (t < 8) ? __shfl_sync(0xffffffffu, v0, 24 + t)
                                   : __shfl_sync(0xffffffffu, v1, t - 8);
                hp = fmaf(fx, ph1[t], hp);
                hp = fmaf(fa, ph2[t], hp);
                lp = fmaf(fx, pl1[t], lp);
                lp = fmaf(fa, pl2[t], lp);
                lp = fmaf(fc, pl3[t], lp);
                rp = fmaf(fx, pg[t], rp);
            }
            float s[6] = {hp, hp * hp, lp, lp * lp, rp, rp * rp};
#pragma unroll
            for (int o = 16; o > 0; o >>= 1) {
#pragma unroll
                for (int i = 0; i < 6; i++) s[i] += __shfl_xor_sync(0xffffffffu, s[i], o);
            }
            if (lane == 0) {
#pragma unroll
                for (int i = 0; i < 6; i++) red[grp][w][i] = s[i];
            }
            asm volatile("bar.sync %0, 64;" ::"r"(grp + 1) : "memory");
            float tot[6];
#pragma unroll
            for (int i = 0; i < 6; i++) tot[i] = red[grp][0][i] + red[grp][1][i];
            const float inv = 1.0f / 64.0f;
            float mh = tot[0] * inv, vh = tot[1] * inv - mh * mh;
            float ml = tot[2] * inv, vl = tot[3] * inv - ml * ml;
            float mr = tot[4] * inv, vr = tot[5] * inv - mr * mr;
            float high = (hp - mh) * rsqrtf(vh + 1e-5f) * ghn + bhn;
            high = (high >= 0.f) ? high : 0.1f * high;
            float lowv = (lp - ml) * rsqrtf(vl + 1e-5f) * gln + bln;
            lowv = 0.5f * lowv * (1.0f + erff(lowv * 0.70710678118654752f));
            float res = (rp - mr) * rsqrtf(vr + 1e-5f) * ggn + bgn;

            float z0 = high * waH0 + lowv * waL0;
            float z1 = high * waH1 + lowv * waL1;
#pragma unroll
            for (int o = 16; o > 0; o >>= 1) {
                z0 += __shfl_xor_sync(0xffffffffu, z0, o);
                z1 += __shfl_xor_sync(0xffffffffu, z1, o);
            }
            if (lane == 0) {
                red[grp][w][6] = z0;
                red[grp][w][7] = z1;
            }
            asm volatile("bar.sync %0, 64;" ::"r"(grp + 1) : "memory");
            float l0 = red[grp][0][6] + red[grp][1][6] + ba0;
            float l1 = red[grp][0][7] + red[grp][1][7] + ba1;
            float a0 = 1.0f / (1.0f + expf(l1 - l0));
            float a1 = 1.0f - a0;
            float fused = a0 * high + a1 * lowv + 0.3f * (high + lowv) + 0.1f * res;
            outs[0][d][j] = fused;
            outs[1][d][j] = high;
            outs[2][d][j] = lowv;
        }
        __syncthreads();
#pragma unroll
        for (int it = 0; it < 6; it++) {
            int idx = it * 512 + tid;
            int jj = idx & 15;
            int dd = (idx >> 4) & 63;
            int a = idx >> 10;
            out[(size_t)a * (Bx * OD * NN) + ((size_t)(b * OD + dd)) * NN + n0 + jj] =
                outs[a][dd][jj];
        }
        __syncthreads();
    }
}

// ---------------- launch ----------------

extern "C" void kernel_launch(void* const* d_in, const int* in_sizes, int n_in, void* d_out,
                              int out_size) {
    const float* x = (const float*)d_in[0];
    const int* ei = (const int*)d_in[1];
    const int* cei = (const int*)d_in[2];
    const float* W_ht = (const float*)d_in[3];
    const float* b_ht = (const float*)d_in[4];
    const float* W_lt = (const float*)d_in[5];
    const float* b_lt = (const float*)d_in[6];
    const float* Ws_h = (const float*)d_in[7];
    const float* Wn_h = (const float*)d_in[8];
    const float* b_h = (const float*)d_in[9];
    const float* Ws_l = (const float*)d_in[10];
    const float* Wn_l = (const float*)d_in[11];
    const float* Wc_l = (const float*)d_in[12];
    const float* b_l = (const float*)d_in[13];
    const float* Whr = (const float*)d_in[14];
    const float* bhr = (const float*)d_in[15];
    const float* Wlr = (const float*)d_in[16];
    const float* blr = (const float*)d_in[17];
    const float* ghn = (const float*)d_in[18];
    const float* bhn = (const float*)d_in[19];
    const float* gln = (const float*)d_in[20];
    const float* bln = (const float*)d_in[21];
    const float* Wa = (const float*)d_in[22];
    const float* ba = (const float*)d_in[23];
    const float* Wg = (const float*)d_in[24];
    const float* bg = (const float*)d_in[25];
    const float* ggn = (const float*)d_in[26];
    const float* bgn = (const float*)d_in[27];
    float* out = (float*)d_out;

    init_kernel<<<TR_BLOCKS + Z_BLOCKS + 4, 256>>>(x, W_ht, b_ht, W_lt, b_lt, Ws_h, Wn_h, b_h,
                                                   Ws_l, Wn_l, Wc_l, b_l, Whr, bhr, Wlr, blr, Wg);
    count_kernel<<<(2 * (EE / 4) + 255) / 256, 256>>>(ei, cei);
    scan_kernel<<<2, 1024>>>();
    fill_kernel<<<(2 * EE + 255) / 256, 256>>>(ei, cei);
    agg_kernel<<<(NN * 32 + 255) / 256, 256>>>();
    final_kernel<<<592, 512>>>(out, bg, ghn, bhn, gln, bln, ggn, bgn, Wa, ba);
}

// round 3
// speedup vs baseline: 1.4953x; 1.1881x over previous
#include <cuda_runtime.h>
#include <math.h>

#define Bx 8
#define Tt 12
#define NN 10000
#define EE 160000
#define OD 64
#define TILE 16
#define NTILES (NN / TILE) /* 625 */

#define NBLK 148
#define NTHR 1024
#define TTHR (NBLK * NTHR) /* 151552 */
#define CHUNK 68           /* 148*68 = 10064 >= NN */

// ---------------- scratch (__device__ globals; no allocation) ----------------
__device__ float g_xT[Bx * NN * 16];    // x transposed to [b][n][16] (12 used)
__device__ float g_aggX[Bx * NN * 16];  // agg of x over normal edges
__device__ float g_aggC[Bx * NN * 16];  // agg of x over causal edges
__device__ int g_rowN[NN + 1];
__device__ int g_rowC[NN + 1];
__device__ int g_colN[EE];
__device__ int g_colC[EE];
__device__ int g_degN[NN];  // zero at start of every run (zeroed by prev run / load)
__device__ int g_degC[NN];
__device__ int g_curN[NN];
__device__ int g_curC[NN];
__device__ int g_psumN[NBLK];
__device__ int g_psumC[NBLK];
__device__ unsigned g_cnt;  // grid-barrier counter; reset by final_kernel
// combined 12x64 weights, stored [d][t] for per-thread register preload
__device__ float g_Ph1[OD * Tt], g_Ph2[OD * Tt];
__device__ float g_Pl1[OD * Tt], g_Pl2[OD * Tt], g_Pl3[OD * Tt];
__device__ float g_Pg[OD * Tt];
__device__ float g_bH0[OD], g_bHm[OD], g_bL0[OD], g_bLm[OD], g_bLc[OD];

// ---------------- software grid barrier (all NBLK blocks co-resident) --------
__device__ __forceinline__ void gbar(unsigned phase) {
    __syncthreads();
    if (threadIdx.x == 0) {
        __threadfence();
        atomicAdd(&g_cnt, 1u);
        unsigned target = NBLK * phase;
        while (*(volatile unsigned*)&g_cnt < target) __nanosleep(64);
        __threadfence();
    }
    __syncthreads();
}

// ---------------- K1: persistent pipeline kernel -----------------------------
__global__ void __launch_bounds__(NTHR, 1) pipeline_kernel(
    const float* __restrict__ x, const int* __restrict__ ei, const int* __restrict__ cei,
    const float* __restrict__ W_ht, const float* __restrict__ b_ht,
    const float* __restrict__ W_lt, const float* __restrict__ b_lt,
    const float* __restrict__ Ws_h, const float* __restrict__ Wn_h,
    const float* __restrict__ b_h, const float* __restrict__ Ws_l,
    const float* __restrict__ Wn_l, const float* __restrict__ Wc_l,
    const float* __restrict__ b_l, const float* __restrict__ Whr,
    const float* __restrict__ bhr, const float* __restrict__ Wlr,
    const float* __restrict__ blr, const float* __restrict__ Wg) {
    const int tid = threadIdx.x;
    const int bid = blockIdx.x;
    const int gtid = bid * NTHR + tid;
    __shared__ int s[256];

    // ===== Phase A: transpose x  |  count degrees (atomics)  |  prep weights
    for (int i = gtid; i < 160832; i += TTHR) {
        if (i < 80000) {
            // transpose: item i = (b, n)
            int b = i / NN;
            int n = i - b * NN;
            float v[16];
#pragma unroll
            for (int t = 0; t < Tt; t++) v[t] = x[((size_t)b * Tt + t) * NN + n];
            v[12] = v[13] = v[14] = v[15] = 0.f;
            float4* dst = (float4*)(g_xT + (size_t)i * 16);
            dst[0] = make_float4(v[0], v[1], v[2], v[3]);
            dst[1] = make_float4(v[4], v[5], v[6], v[7]);
            dst[2] = make_float4(v[8], v[9], v[10], v[11]);
            dst[3] = make_float4(v[12], v[13], v[14], v[15]);
        } else if (i < 160000) {
            int q = i - 80000;  // 0..79999 int4 units; first 40000 normal, rest causal
            if (q < 40000) {
                int4 v = ((const int4*)(ei + EE))[q];
                atomicAdd(&g_degN[v.x], 1);
                atomicAdd(&g_degN[v.y], 1);
                atomicAdd(&g_degN[v.z], 1);
                atomicAdd(&g_degN[v.w], 1);
            } else {
                int4 v = ((const int4*)(cei + EE))[q - 40000];
                atomicAdd(&g_degC[v.x], 1);
                atomicAdd(&g_degC[v.y], 1);
                atomicAdd(&g_degC[v.z], 1);
                atomicAdd(&g_degC[v.w], 1);
            }
        } else {
            int pid = i - 160000;  // 0..831
            int t = pid >> 6;
            int d = pid & 63;
            if (t < Tt) {
                float s1 = 0.f, s2 = 0.f, s3 = 0.f, s4 = 0.f, s5 = 0.f;
                for (int k = 0; k < 64; k++) {
                    float wht = W_ht[t * 64 + k];
                    float wlt = W_lt[t * 64 + k];
                    s1 += wht * (Ws_h[k * 64 + d] + 0.2f * Whr[k * 64 + d]);
                    s2 += wht * Wn_h[k * 64 + d];
                    s3 += wlt * (Ws_l[k * 64 + d] + 0.2f * Wlr[k * 64 + d]);
                    s4 += wlt * Wn_l[k * 64 + d];
                    s5 += wlt * Wc_l[k * 64 + d];
                }
                g_Ph1[d * Tt + t] = s1;
                g_Ph2[d * Tt + t] = s2;
                g_Pl1[d * Tt + t] = s3;
                g_Pl2[d * Tt + t] = s4;
                g_Pl3[d * Tt + t] = s5;
                g_Pg[d * Tt + t] = 2.0f * Wg[t * 64 + d];  // x_for_residual = 2x
            } else {
                float bh0 = b_h[d] + 0.2f * bhr[d];
                float bhm = 0.f;
                float bl0 = b_l[d] + 0.2f * blr[d];
                float blm = 0.f, blc = 0.f;
                for (int k = 0; k < 64; k++) {
                    bh0 += b_ht[k] * (Ws_h[k * 64 + d] + 0.2f * Whr[k * 64 + d]);
                    bhm += b_ht[k] * Wn_h[k * 64 + d];
                    bl0 += b_lt[k] * (Ws_l[k * 64 + d] + 0.2f * Wlr[k * 64 + d]);
                    blm += b_lt[k] * Wn_l[k * 64 + d];
                    blc += b_lt[k] * Wc_l[k * 64 + d];
                }
                g_bH0[d] = bh0;
                g_bHm[d] = bhm;
                g_bL0[d] = bl0;
                g_bLm[d] = blm;
                g_bLc[d] = blc;
            }
        }
    }
    gbar(1);

    // ===== Phase B1: per-block partial sums of degrees (chunk of 68 nodes)
    {
        int base = bid * CHUNK;
        if (tid < 68)
            s[tid] = (base + tid < NN) ? g_degN[base + tid] : 0;
        else if (tid < 128)
            s[tid] = 0;
        else if (tid < 196)
            s[tid] = (base + tid - 128 < NN) ? g_degC[base + tid - 128] : 0;
        else if (tid < 256)
            s[tid] = 0;
        __syncthreads();
#pragma unroll
        for (int off = 64; off > 0; off >>= 1) {
            if (tid < off)
                s[tid] += s[tid + off];
            else if (tid >= 128 && tid < 128 + off)
                s[tid] += s[tid + off];
            __syncthreads();
        }
        if (tid == 0) g_psumN[bid] = s[0];
        if (tid == 128) g_psumC[bid] = s[128];
    }
    gbar(2);

    // ===== Phase B2: exclusive scan of 148 partials (block 0, warps 0 and 1)
    if (bid == 0 && tid < 64) {
        int lane = tid & 31;
        int* p = (tid < 32) ? g_psumN : g_psumC;
        int carry = 0;
        for (int k = 0; k < 5; k++) {
            int i = k * 32 + lane;
            int v = (i < NBLK) ? p[i] : 0;
            int inc = v;
#pragma unroll
            for (int o = 1; o < 32; o <<= 1) {
                int u = __shfl_up_sync(0xffffffffu, inc, o);
                if (lane >= o) inc += u;
            }
            if (i < NBLK) p[i] = carry + inc - v;  // exclusive
            carry += __shfl_sync(0xffffffffu, inc, 31);
        }
    }
    gbar(3);

    // ===== Phase B3: local inclusive scan -> row offsets
    {
        int base = bid * CHUNK;
        if (tid < 68)
            s[tid] = (base + tid < NN) ? g_degN[base + tid] : 0;
        else if (tid < 128)
            s[tid] = 0;
        else if (tid < 196)
            s[tid] = (base + tid - 128 < NN) ? g_degC[base + tid - 128] : 0;
        else if (tid < 256)
            s[tid] = 0;
        __syncthreads();
#pragma unroll
        for (int off = 1; off < 128; off <<= 1) {
            int v = 0;
            if (tid < 256 && (tid & 127) >= off) v = s[tid - off];
            __syncthreads();
            if (tid < 256) s[tid] += v;
            __syncthreads();
        }
        if (tid < 68) {
            int n = base + tid;
            if (n < NN) g_rowN[n + 1] = g_psumN[bid] + s[tid];
        } else if (tid >= 128 && tid < 196) {
            int n = base + tid - 128;
            if (n < NN) g_rowC[n + 1] = g_psumC[bid] + s[tid];
        }
        if (bid == 0 && tid == 0) {
            g_rowN[0] = 0;
            g_rowC[0] = 0;
        }
    }
    gbar(4);

    // ===== Phase C: fill CSR columns
    for (int i = gtid; i < 2 * EE; i += TTHR) {
        if (i < EE) {
            int dd = __ldg(&ei[EE + i]);
            int p = atomicAdd(&g_curN[dd], 1);
            g_colN[g_rowN[dd] + p] = __ldg(&ei[i]);
        } else {
            int j = i - EE;
            int dd = __ldg(&cei[EE + j]);
            int p = atomicAdd(&g_curC[dd], 1);
            g_colC[g_rowC[dd] + p] = __ldg(&cei[j]);
        }
    }
    gbar(5);

    // ===== Phase D: gather-aggregate + cleanup (zero deg/cur for next run)
    for (int idx = gtid; idx < 330000; idx += TTHR) {
        if (idx < 320000) {
            int t = idx & 15;
            if (t >= Tt) continue;
            int n = idx >> 4;
            int causal = (n >= NN);
            if (causal) n -= NN;
            const int* __restrict__ row = causal ? g_rowC : g_rowN;
            const int* __restrict__ col = causal ? g_colC : g_colN;
            float* __restrict__ dst = causal ? g_aggC : g_aggX;
            int rs = row[n], re = row[n + 1];
            float acc[Bx];
#pragma unroll
            for (int b = 0; b < Bx; b++) acc[b] = 0.f;
#pragma unroll 2
            for (int e = rs; e < re; e++) {
                int c = __ldg(&col[e]);
                const float* p = g_xT + c * 16 + t;
#pragma unroll
                for (int b = 0; b < Bx; b++) acc[b] += __ldg(&p[b * NN * 16]);
            }
            float invd = 1.0f / fmaxf((float)(re - rs), 1.0f);
#pragma unroll
            for (int b = 0; b < Bx; b++) dst[b * NN * 16 + n * 16 + t] = acc[b] * invd;
        } else {
            int z = idx - 320000;  // 0..9999: zero deg/cur (int4 granularity)
            int a = z / 2500;
            int r = z - a * 2500;
            int4 zv = make_int4(0, 0, 0, 0);
            if (a == 0)
                ((int4*)g_degN)[r] = zv;
            else if (a == 1)
                ((int4*)g_degC)[r] = zv;
            else if (a == 2)
                ((int4*)g_curN)[r] = zv;
            else
                ((int4*)g_curC)[r] = zv;
        }
    }
    // no trailing barrier: kernel boundary orders phase D before final_kernel
}

// ---------------- K2: fused epilogue -----------------------------------------
// 512 threads = 8 independent 64-thread node-groups. Per-node sync via named
// barriers (bar.sync grp+1, 64) only; block-wide sync only around output stage.
__global__ void __launch_bounds__(512, 1) final_kernel(
    float* __restrict__ out, const float* __restrict__ bg, const float* __restrict__ ghn_,
    const float* __restrict__ bhn_, const float* __restrict__ gln_, const float* __restrict__ bln_,
    const float* __restrict__ ggn_, const float* __restrict__ bgn_, const float* __restrict__ Wa,
    const float* __restrict__ ba) {
    int tid = threadIdx.x;
    if (blockIdx.x == 0 && tid == 0) g_cnt = 0;  // reset grid barrier for next replay
    int d = tid & 63;
    int grp = tid >> 6;      // 0..7
    int w = (tid >> 5) & 1;  // warp within group
    int lane = tid & 31;

    float ph1[Tt], ph2[Tt], pl1[Tt], pl2[Tt], pl3[Tt], pg[Tt];
#pragma unroll
    for (int t = 0; t < Tt; t++) {
        ph1[t] = g_Ph1[d * Tt + t];
        ph2[t] = g_Ph2[d * Tt + t];
        pl1[t] = g_Pl1[d * Tt + t];
        pl2[t] = g_Pl2[d * Tt + t];
        pl3[t] = g_Pl3[d * Tt + t];
        pg[t] = g_Pg[d * Tt + t];
    }
    float bH0 = g_bH0[d], bHm = g_bHm[d], bL0 = g_bL0[d], bLm = g_bLm[d], bLc = g_bLc[d];
    float bgd = bg[d];
    float ghn = ghn_[d], bhn = bhn_[d], gln = gln_[d], bln = bln_[d], ggn = ggn_[d], bgn = bgn_[d];
    float waH0 = Wa[d * 2 + 0], waH1 = Wa[d * 2 + 1];
    float waL0 = Wa[(64 + d) * 2 + 0], waL1 = Wa[(64 + d) * 2 + 1];
    float ba0 = ba[0], ba1 = ba[1];

    __shared__ float red[8][2][8];
    __shared__ float outs[3][64][17];  // pad 17 -> conflict-free

    int ntot = Bx * NTILES;
    for (int tile = blockIdx.x; tile < ntot; tile += gridDim.x) {
        int b = tile / NTILES;
        int n0 = (tile - b * NTILES) * TILE;
#pragma unroll
        for (int rep = 0; rep < 2; rep++) {
            int j = rep * 8 + grp;
            int n = n0 + j;
            int base = (b * NN + n) * 16;
            // lane-mapped feature load (each warp of the group loads its own copy)
            float v0 = (lane < 12)   ? g_xT[base + lane]
                       : (lane < 24) ? g_aggX[base + lane - 12]
                                     : g_aggC[base + lane - 24];
            float v1 = 0.f;
            if (lane < 4)
                v1 = g_aggC[base + 8 + lane];
            else if (lane == 4)
                v1 = (g_rowN[n + 1] > g_rowN[n]) ? 1.f : 0.f;
            else if (lane == 5)
                v1 = (g_rowC[n + 1] > g_rowC[n]) ? 1.f : 0.f;

            float m = __shfl_sync(0xffffffffu, v1, 4);
            float mc = __shfl_sync(0xffffffffu, v1, 5);
            float hp = bH0 + m * bHm;
            float lp = bL0 + m * bLm + mc * bLc;
            float rp = bgd;
#pragma unroll
            for (int t = 0; t < Tt; t++) {
                float fx = __shfl_sync(0xffffffffu, v0, t);
                float fa = __shfl_sync(0xffffffffu, v0, 12 + t);
                float fc = (t < 8) ? __shfl_sync(0xffffffffu, v0, 24 + t)
                                   : __shfl_sync(0xffffffffu, v1, t - 8);
                hp = fmaf(fx, ph1[t], hp);
                hp = fmaf(fa, ph2[t], hp);
                lp = fmaf(fx, pl1[t], lp);
                lp = fmaf(fa, pl2[t], lp);
                lp = fmaf(fc, pl3[t], lp);
                rp = fmaf(fx, pg[t], rp);
            }
            float sr[6] = {hp, hp * hp, lp, lp * lp, rp, rp * rp};
#pragma unroll
            for (int o = 16; o > 0; o >>= 1) {
#pragma unroll
                for (int i = 0; i < 6; i++) sr[i] += __shfl_xor_sync(0xffffffffu, sr[i], o);
            }
            if (lane == 0) {
#pragma unroll
                for (int i = 0; i < 6; i++) red[grp][w][i] = sr[i];
            }
            asm volatile("bar.sync %0, 64;" ::"r"(grp + 1) : "memory");
            float tot[6];
#pragma unroll
            for (int i = 0; i < 6; i++) tot[i] = red[grp][0][i] + red[grp][1][i];
            const float inv = 1.0f / 64.0f;
            float mh = tot[0] * inv, vh = tot[1] * inv - mh * mh;
            float ml = tot[2] * inv, vl = tot[3] * inv - ml * ml;
            float mr = tot[4] * inv, vr = tot[5] * inv - mr * mr;
            float high = (hp - mh) * rsqrtf(vh + 1e-5f) * ghn + bhn;
            high = (high >= 0.f) ? high : 0.1f * high;
            float lowv = (lp - ml) * rsqrtf(vl + 1e-5f) * gln + bln;
            lowv = 0.5f * lowv * (1.0f + erff(lowv * 0.70710678118654752f));
            float res = (rp - mr) * rsqrtf(vr + 1e-5f) * ggn + bgn;

            float z0 = high * waH0 + lowv * waL0;
            float z1 = high * waH1 + lowv * waL1;
#pragma unroll
            for (int o = 16; o > 0; o >>= 1) {
                z0 += __shfl_xor_sync(0xffffffffu, z0, o);
                z1 += __shfl_xor_sync(0xffffffffu, z1, o);
            }
            if (lane == 0) {
                red[grp][w][6] = z0;
                red[grp][w][7] = z1;
            }
            asm volatile("bar.sync %0, 64;" ::"r"(grp + 1) : "memory");
            float l0 = red[grp][0][6] + red[grp][1][6] + ba0;
            float l1 = red[grp][0][7] + red[grp][1][7] + ba1;
            float a0 = 1.0f / (1.0f + expf(l1 - l0));
            float a1 = 1.0f - a0;
            float fused = a0 * high + a1 * lowv + 0.3f * (high + lowv) + 0.1f * res;
            outs[0][d][j] = fused;
            outs[1][d][j] = high;
            outs[2][d][j] = lowv;
        }
        __syncthreads();
#pragma unroll
        for (int it = 0; it < 6; it++) {
            int idx = it * 512 + tid;
            int jj = idx & 15;
            int dd = (idx >> 4) & 63;
            int a = idx >> 10;
            out[(size_t)a * (Bx * OD * NN) + ((size_t)(b * OD + dd)) * NN + n0 + jj] =
                outs[a][dd][jj];
        }
        __syncthreads();
    }
}

// ---------------- launch ------------------------------------------------------

extern "C" void kernel_launch(void* const* d_in, const int* in_sizes, int n_in, void* d_out,
                              int out_size) {
    const float* x = (const float*)d_in[0];
    const int* ei = (const int*)d_in[1];
    const int* cei = (const int*)d_in[2];
    const float* W_ht = (const float*)d_in[3];
    const float* b_ht = (const float*)d_in[4];
    const float* W_lt = (const float*)d_in[5];
    const float* b_lt = (const float*)d_in[6];
    const float* Ws_h = (const float*)d_in[7];
    const float* Wn_h = (const float*)d_in[8];
    const float* b_h = (const float*)d_in[9];
    const float* Ws_l = (const float*)d_in[10];
    const float* Wn_l = (const float*)d_in[11];
    const float* Wc_l = (const float*)d_in[12];
    const float* b_l = (const float*)d_in[13];
    const float* Whr = (const float*)d_in[14];
    const float* bhr = (const float*)d_in[15];
    const float* Wlr = (const float*)d_in[16];
    const float* blr = (const float*)d_in[17];
    const float* ghn = (const float*)d_in[18];
    const float* bhn = (const float*)d_in[19];
    const float* gln = (const float*)d_in[20];
    const float* bln = (const float*)d_in[21];
    const float* Wa = (const float*)d_in[22];
    const float* ba = (const float*)d_in[23];
    const float* Wg = (const float*)d_in[24];
    const float* bg = (const float*)d_in[25];
    const float* ggn = (const float*)d_in[26];
    const float* bgn = (const float*)d_in[27];
    float* out = (float*)d_out;

    pipeline_kernel<<<NBLK, NTHR>>>(x, ei, cei, W_ht, b_ht, W_lt, b_lt, Ws_h, Wn_h, b_h, Ws_l,
                                    Wn_l, Wc_l, b_l, Whr, bhr, Wlr, blr, Wg);
    final_kernel<<<NBLK, 512>>>(out, bg, ghn, bhn, gln, bln, ggn, bgn, Wa, ba);
}

// round 4
// speedup vs baseline: 1.7544x; 1.1732x over previous
#include <cuda_runtime.h>
#include <math.h>

#define Bx 8
#define Tt 12
#define NN 10000
#define EE 160000
#define OD 64

#define NBLK 148
#define NTHR 1024
#define TTHR (NBLK * NTHR) /* 151552 */
#define CHUNK 68           /* 148*68 = 10064 >= NN */

// ---------------- scratch (__device__ globals; no allocation) ----------------
__device__ float g_xT[Bx * NN * 16];     // compact x^T [f][16] (12 used) for gather
__device__ float g_xT2[Bx * NN * 24];    // duplicated {v,v} pairs [f][24]
__device__ float g_aggX2[Bx * NN * 24];  // duplicated agg (normal)
__device__ float g_aggC2[Bx * NN * 24];  // duplicated agg (causal)
__device__ float2 g_mflag[NN];           // {degN>0, degC>0}
__device__ int g_rowN[NN + 1];
__device__ int g_rowC[NN + 1];
__device__ int g_colN[EE];
__device__ int g_colC[EE];
__device__ int g_degN[NN];
__device__ int g_degC[NN];
__device__ int g_curN[NN];
__device__ int g_curC[NN];
__device__ int g_psumN[NBLK];
__device__ int g_psumC[NBLK];
__device__ unsigned g_cnt;  // grid-barrier counter; reset by final_kernel
// packed combined weights: 3 banks of [12][32] float4
//  A[t][l] = {Ph1[t][l], Ph1[t][l+32], Ph2[t][l], Ph2[t][l+32]}
//  B[t][l] = {Pl1.., Pl2..}   C[t][l] = {Pl3.., Pg..}
__device__ float g_Wpk[3 * 12 * 32 * 4];
__device__ float g_bH0[OD], g_bHm[OD], g_bL0[OD], g_bLm[OD], g_bLc[OD];

// ---------------- f32x2 helpers ----------------
#define FMA2(d, a, b) asm("fma.rn.f32x2 %0, %1, %2, %0;" : "+l"(d) : "l"(a), "l"(b))

__device__ __forceinline__ unsigned long long PK2(float lo, float hi) {
    unsigned long long r;
    asm("mov.b64 %0, {%1, %2};" : "=l"(r) : "f"(lo), "f"(hi));
    return r;
}
__device__ __forceinline__ void UPK2(float& lo, float& hi, unsigned long long v) {
    asm("mov.b64 {%0, %1}, %2;" : "=f"(lo), "=f"(hi) : "l"(v));
}

// ---------------- software grid barrier (all NBLK blocks co-resident) --------
__device__ __forceinline__ void gbar(unsigned phase) {
    __syncthreads();
    if (threadIdx.x == 0) {
        __threadfence();
        atomicAdd(&g_cnt, 1u);
        unsigned target = NBLK * phase;
        while (*(volatile unsigned*)&g_cnt < target) __nanosleep(64);
        __threadfence();
    }
    __syncthreads();
}

// ---------------- K1: persistent pipeline kernel -----------------------------
__global__ void __launch_bounds__(NTHR, 1) pipeline_kernel(
    const float* __restrict__ x, const int* __restrict__ ei, const int* __restrict__ cei,
    const float* __restrict__ W_ht, const float* __restrict__ b_ht,
    const float* __restrict__ W_lt, const float* __restrict__ b_lt,
    const float* __restrict__ Ws_h, const float* __restrict__ Wn_h,
    const float* __restrict__ b_h, const float* __restrict__ Ws_l,
    const float* __restrict__ Wn_l, const float* __restrict__ Wc_l,
    const float* __restrict__ b_l, const float* __restrict__ Whr,
    const float* __restrict__ bhr, const float* __restrict__ Wlr,
    const float* __restrict__ blr, const float* __restrict__ Wg) {
    const int tid = threadIdx.x;
    const int bid = blockIdx.x;
    const int gtid = bid * NTHR + tid;
    __shared__ int s[256];

    // ===== Phase A: transpose x  |  count degrees (atomics)  |  prep weights
    for (int i = gtid; i < 160832; i += TTHR) {
        if (i < 80000) {
            int b = i / NN;
            int n = i - b * NN;
            float v[12];
#pragma unroll
            for (int t = 0; t < Tt; t++) v[t] = x[((size_t)b * Tt + t) * NN + n];
            float4* dst = (float4*)(g_xT + (size_t)i * 16);
            dst[0] = make_float4(v[0], v[1], v[2], v[3]);
            dst[1] = make_float4(v[4], v[5], v[6], v[7]);
            dst[2] = make_float4(v[8], v[9], v[10], v[11]);
            dst[3] = make_float4(0.f, 0.f, 0.f, 0.f);
            float4* d2 = (float4*)(g_xT2 + (size_t)i * 24);
#pragma unroll
            for (int c = 0; c < 6; c++)
                d2[c] = make_float4(v[2 * c], v[2 * c], v[2 * c + 1], v[2 * c + 1]);
        } else if (i < 160000) {
            int q = i - 80000;
            if (q < 40000) {
                int4 v = ((const int4*)(ei + EE))[q];
                atomicAdd(&g_degN[v.x], 1);
                atomicAdd(&g_degN[v.y], 1);
                atomicAdd(&g_degN[v.z], 1);
                atomicAdd(&g_degN[v.w], 1);
            } else {
                int4 v = ((const int4*)(cei + EE))[q - 40000];
                atomicAdd(&g_degC[v.x], 1);
                atomicAdd(&g_degC[v.y], 1);
                atomicAdd(&g_degC[v.z], 1);
                atomicAdd(&g_degC[v.w], 1);
            }
        } else {
            int pid = i - 160000;  // 0..831
            int t = pid >> 6;
            int d = pid & 63;
            int dl = d & 31;
            int hi = d >> 5;
            if (t < Tt) {
                float s1 = 0.f, s2 = 0.f, s3 = 0.f, s4 = 0.f, s5 = 0.f;
                for (int k = 0; k < 64; k++) {
                    float wht = W_ht[t * 64 + k];
                    float wlt = W_lt[t * 64 + k];
                    s1 += wht * (Ws_h[k * 64 + d] + 0.2f * Whr[k * 64 + d]);
                    s2 += wht * Wn_h[k * 64 + d];
                    s3 += wlt * (Ws_l[k * 64 + d] + 0.2f * Wlr[k * 64 + d]);
                    s4 += wlt * Wn_l[k * 64 + d];
                    s5 += wlt * Wc_l[k * 64 + d];
                }
                int base = (t * 32 + dl) * 4;
                g_Wpk[base + hi] = s1;
                g_Wpk[base + 2 + hi] = s2;
                g_Wpk[1536 + base + hi] = s3;
                g_Wpk[1536 + base + 2 + hi] = s4;
                g_Wpk[3072 + base + hi] = s5;
                g_Wpk[3072 + base + 2 + hi] = 2.0f * Wg[t * 64 + d];  // x_res = 2x
            } else {
                float bh0 = b_h[d] + 0.2f * bhr[d];
                float bhm = 0.f;
                float bl0 = b_l[d] + 0.2f * blr[d];
                float blm = 0.f, blc = 0.f;
                for (int k = 0; k < 64; k++) {
                    bh0 += b_ht[k] * (Ws_h[k * 64 + d] + 0.2f * Whr[k * 64 + d]);
                    bhm += b_ht[k] * Wn_h[k * 64 + d];
                    bl0 += b_lt[k] * (Ws_l[k * 64 + d] + 0.2f * Wlr[k * 64 + d]);
                    blm += b_lt[k] * Wn_l[k * 64 + d];
                    blc += b_lt[k] * Wc_l[k * 64 + d];
                }
                g_bH0[d] = bh0;
                g_bHm[d] = bhm;
                g_bL0[d] = bl0;
                g_bLm[d] = blm;
                g_bLc[d] = blc;
            }
        }
    }
    gbar(1);

    // ===== Phase B1: per-block partial sums of degrees
    {
        int base = bid * CHUNK;
        if (tid < 68)
            s[tid] = (base + tid < NN) ? g_degN[base + tid] : 0;
        else if (tid < 128)
            s[tid] = 0;
        else if (tid < 196)
            s[tid] = (base + tid - 128 < NN) ? g_degC[base + tid - 128] : 0;
        else if (tid < 256)
            s[tid] = 0;
        __syncthreads();
#pragma unroll
        for (int off = 64; off > 0; off >>= 1) {
            if (tid < off)
                s[tid] += s[tid + off];
            else if (tid >= 128 && tid < 128 + off)
                s[tid] += s[tid + off];
            __syncthreads();
        }
        if (tid == 0) g_psumN[bid] = s[0];
        if (tid == 128) g_psumC[bid] = s[128];
    }
    gbar(2);

    // ===== Phase B2: exclusive scan of 148 partials
    if (bid == 0 && tid < 64) {
        int lane = tid & 31;
        int* p = (tid < 32) ? g_psumN : g_psumC;
        int carry = 0;
        for (int k = 0; k < 5; k++) {
            int i = k * 32 + lane;
            int v = (i < NBLK) ? p[i] : 0;
            int inc = v;
#pragma unroll
            for (int o = 1; o < 32; o <<= 1) {
                int u = __shfl_up_sync(0xffffffffu, inc, o);
                if (lane >= o) inc += u;
            }
            if (i < NBLK) p[i] = carry + inc - v;
            carry += __shfl_sync(0xffffffffu, inc, 31);
        }
    }
    gbar(3);

    // ===== Phase B3: local inclusive scan -> row offsets
    {
        int base = bid * CHUNK;
        if (tid < 68)
            s[tid] = (base + tid < NN) ? g_degN[base + tid] : 0;
        else if (tid < 128)
            s[tid] = 0;
        else if (tid < 196)
            s[tid] = (base + tid - 128 < NN) ? g_degC[base + tid - 128] : 0;
        else if (tid < 256)
            s[tid] = 0;
        __syncthreads();
#pragma unroll
        for (int off = 1; off < 128; off <<= 1) {
            int v = 0;
            if (tid < 256 && (tid & 127) >= off) v = s[tid - off];
            __syncthreads();
            if (tid < 256) s[tid] += v;
            __syncthreads();
        }
        if (tid < 68) {
            int n = base + tid;
            if (n < NN) g_rowN[n + 1] = g_psumN[bid] + s[tid];
        } else if (tid >= 128 && tid < 196) {
            int n = base + tid - 128;
            if (n < NN) g_rowC[n + 1] = g_psumC[bid] + s[tid];
        }
        if (bid == 0 && tid == 0) {
            g_rowN[0] = 0;
            g_rowC[0] = 0;
        }
    }
    gbar(4);

    // ===== Phase C: fill CSR columns
    for (int i = gtid; i < 2 * EE; i += TTHR) {
        if (i < EE) {
            int dd = __ldg(&ei[EE + i]);
            int p = atomicAdd(&g_curN[dd], 1);
            g_colN[g_rowN[dd] + p] = __ldg(&ei[i]);
        } else {
            int j = i - EE;
            int dd = __ldg(&cei[EE + j]);
            int p = atomicAdd(&g_curC[dd], 1);
            g_colC[g_rowC[dd] + p] = __ldg(&cei[j]);
        }
    }
    gbar(5);

    // ===== Phase D: gather-aggregate (dup output) + mflag + cleanup
    for (int idx = gtid; idx < 340000; idx += TTHR) {
        if (idx < 320000) {
            int t = idx & 15;
            if (t >= Tt) continue;
            int n = idx >> 4;
            int causal = (n >= NN);
            if (causal) n -= NN;
            const int* __restrict__ row = causal ? g_rowC : g_rowN;
            const int* __restrict__ col = causal ? g_colC : g_colN;
            float2* __restrict__ dst = (float2*)(causal ? g_aggC2 : g_aggX2);
            int rs = row[n], re = row[n + 1];
            float acc[Bx];
#pragma unroll
            for (int b = 0; b < Bx; b++) acc[b] = 0.f;
#pragma unroll 2
            for (int e = rs; e < re; e++) {
                int c = __ldg(&col[e]);
                const float* p = g_xT + c * 16 + t;
#pragma unroll
                for (int b = 0; b < Bx; b++) acc[b] += __ldg(&p[b * NN * 16]);
            }
            float invd = 1.0f / fmaxf((float)(re - rs), 1.0f);
#pragma unroll
            for (int b = 0; b < Bx; b++) {
                float v = acc[b] * invd;
                dst[(size_t)(b * NN + n) * 12 + t] = make_float2(v, v);
            }
        } else if (idx < 330000) {
            int z = idx - 320000;  // zero deg/cur (int4 granularity)
            int a = z / 2500;
            int r = z - a * 2500;
            int4 zv = make_int4(0, 0, 0, 0);
            if (a == 0)
                ((int4*)g_degN)[r] = zv;
            else if (a == 1)
                ((int4*)g_degC)[r] = zv;
            else if (a == 2)
                ((int4*)g_curN)[r] = zv;
            else
                ((int4*)g_curC)[r] = zv;
        } else {
            int n = idx - 330000;  // mflag from persistent row arrays
            g_mflag[n] = make_float2((g_rowN[n + 1] > g_rowN[n]) ? 1.f : 0.f,
                                     (g_rowC[n + 1] > g_rowC[n]) ? 1.f : 0.f);
        }
    }
}

// ---------------- K2: fused epilogue (warp-autonomous, f32x2) -----------------
// One warp processes 4 nodes; each thread owns dims (lane, lane+32) packed in
// f32x2. All reductions are warp-local butterflies. No block-level coupling.
#define FW_THR 512
#define TOT_WARPS (NBLK * (FW_THR / 32)) /* 2368 */

__global__ void __launch_bounds__(FW_THR, 1) final_kernel(
    float* __restrict__ out, const float* __restrict__ bg, const float* __restrict__ ghn_,
    const float* __restrict__ bhn_, const float* __restrict__ gln_, const float* __restrict__ bln_,
    const float* __restrict__ ggn_, const float* __restrict__ bgn_, const float* __restrict__ Wa,
    const float* __restrict__ ba) {
    const int tid = threadIdx.x;
    if (blockIdx.x == 0 && tid == 0) g_cnt = 0;  // reset grid barrier for next replay
    const int lane = tid & 31;
    const int wid = tid >> 5;

    __shared__ ulonglong2 sW[1152];  // [A|B|C][t][lane] packed weight pairs
    for (int i = tid; i < 1152; i += FW_THR) sW[i] = ((const ulonglong2*)g_Wpk)[i];
    __syncthreads();

    // per-dim constants (lo = lane, hi = lane+32)
    const int dl = lane, dh = lane + 32;
    float bH0l = g_bH0[dl], bH0h = g_bH0[dh], bHml = g_bHm[dl], bHmh = g_bHm[dh];
    float bL0l = g_bL0[dl], bL0h = g_bL0[dh], bLml = g_bLm[dl], bLmh = g_bLm[dh];
    float bLcl = g_bLc[dl], bLch = g_bLc[dh];
    float bgl = bg[dl], bgh = bg[dh];
    float ghnl = ghn_[dl], ghnh = ghn_[dh], bhnl = bhn_[dl], bhnh = bhn_[dh];
    float glnl = gln_[dl], glnh = gln_[dh], blnl = bln_[dl], blnh = bln_[dh];
    float ggnl = ggn_[dl], ggnh = ggn_[dh], bgnl = bgn_[dl], bgnh = bgn_[dh];
    float waH0l = Wa[dl * 2], waH0h = Wa[dh * 2], waH1l = Wa[dl * 2 + 1], waH1h = Wa[dh * 2 + 1];
    float waL0l = Wa[(64 + dl) * 2], waL0h = Wa[(64 + dh) * 2];
    float waL1l = Wa[(64 + dl) * 2 + 1], waL1h = Wa[(64 + dh) * 2 + 1];
    float ba0 = ba[0], ba1 = ba[1];
    const size_t AS = (size_t)Bx * OD * NN;

    for (int g = blockIdx.x * (FW_THR / 32) + wid; g < 20000; g += TOT_WARPS) {
        int f0 = g * 4;  // 4 flat nodes, same b (NN % 4 == 0)
        int b = f0 / NN;
        int n0 = f0 - b * NN;

        unsigned long long hp[4], lp[4], rp[4];
#pragma unroll
        for (int k = 0; k < 4; k++) {
            float2 mf = g_mflag[n0 + k];
            hp[k] = PK2(fmaf(mf.x, bHml, bH0l), fmaf(mf.x, bHmh, bH0h));
            lp[k] = PK2(fmaf(mf.y, bLcl, fmaf(mf.x, bLml, bL0l)),
                        fmaf(mf.y, bLch, fmaf(mf.x, bLmh, bL0h)));
            rp[k] = PK2(bgl, bgh);
        }
        const ulonglong2* fx0 = (const ulonglong2*)g_xT2 + (size_t)f0 * 6;
        const ulonglong2* fa0 = (const ulonglong2*)g_aggX2 + (size_t)f0 * 6;
        const ulonglong2* fc0 = (const ulonglong2*)g_aggC2 + (size_t)f0 * 6;
#pragma unroll
        for (int c = 0; c < 6; c++) {
            ulonglong2 wA0 = sW[(2 * c) * 32 + lane];
            ulonglong2 wB0 = sW[384 + (2 * c) * 32 + lane];
            ulonglong2 wC0 = sW[768 + (2 * c) * 32 + lane];
            ulonglong2 wA1 = sW[(2 * c + 1) * 32 + lane];
            ulonglong2 wB1 = sW[384 + (2 * c + 1) * 32 + lane];
            ulonglong2 wC1 = sW[768 + (2 * c + 1) * 32 + lane];
#pragma unroll
            for (int k = 0; k < 4; k++) {
                ulonglong2 qx = fx0[k * 6 + c];  // {t0 pair, t1 pair} (uniform)
                ulonglong2 qa = fa0[k * 6 + c];
                ulonglong2 qc = fc0[k * 6 + c];
                FMA2(hp[k], qx.x, wA0.x);
                FMA2(hp[k], qa.x, wA0.y);
                FMA2(lp[k], qx.x, wB0.x);
                FMA2(lp[k], qa.x, wB0.y);
                FMA2(lp[k], qc.x, wC0.x);
                FMA2(rp[k], qx.x, wC0.y);
                FMA2(hp[k], qx.y, wA1.x);
                FMA2(hp[k], qa.y, wA1.y);
                FMA2(lp[k], qx.y, wB1.x);
                FMA2(lp[k], qa.y, wB1.y);
                FMA2(lp[k], qc.y, wC1.x);
                FMA2(rp[k], qx.y, wC1.y);
            }
        }

        float F0[4], F1[4], F2[4], F3[4], F4[4], F5[4];
#pragma unroll
        for (int k = 0; k < 4; k++) {
            float hl, hh, ll, lh, rl, rh;
            UPK2(hl, hh, hp[k]);
            UPK2(ll, lh, lp[k]);
            UPK2(rl, rh, rp[k]);
            float s0 = hl + hh, s1 = fmaf(hl, hl, hh * hh);
            float s2 = ll + lh, s3 = fmaf(ll, ll, lh * lh);
            float s4 = rl + rh, s5 = fmaf(rl, rl, rh * rh);
#pragma unroll
            for (int o = 16; o > 0; o >>= 1) {
                s0 += __shfl_xor_sync(0xffffffffu, s0, o);
                s1 += __shfl_xor_sync(0xffffffffu, s1, o);
                s2 += __shfl_xor_sync(0xffffffffu, s2, o);
                s3 += __shfl_xor_sync(0xffffffffu, s3, o);
                s4 += __shfl_xor_sync(0xffffffffu, s4, o);
                s5 += __shfl_xor_sync(0xffffffffu, s5, o);
            }
            const float inv = 1.0f / 64.0f;
            float mh = s0 * inv, vh = s1 * inv - mh * mh;
            float ml = s2 * inv, vl = s3 * inv - ml * ml;
            float mr = s4 * inv, vr = s5 * inv - mr * mr;
            float rhv = rsqrtf(vh + 1e-5f), rlv = rsqrtf(vl + 1e-5f), rrv = rsqrtf(vr + 1e-5f);
            float highl = fmaf((hl - mh) * rhv, ghnl, bhnl);
            float highh = fmaf((hh - mh) * rhv, ghnh, bhnh);
            highl = (highl >= 0.f) ? highl : 0.1f * highl;
            highh = (highh >= 0.f) ? highh : 0.1f * highh;
            float lwl = fmaf((ll - ml) * rlv, glnl, blnl);
            float lwh = fmaf((lh - ml) * rlv, glnh, blnh);
            float lowl = 0.5f * lwl * (1.0f + erff(lwl * 0.70710678118654752f));
            float lowh = 0.5f * lwh * (1.0f + erff(lwh * 0.70710678118654752f));
            float resl = fmaf((rl - mr) * rrv, ggnl, bgnl);
            float resh = fmaf((rh - mr) * rrv, ggnh, bgnh);

            float z0 = highl * waH0l + highh * waH0h + lowl * waL0l + lowh * waL0h;
            float z1 = highl * waH1l + highh * waH1h + lowl * waL1l + lowh * waL1h;
#pragma unroll
            for (int o = 16; o > 0; o >>= 1) {
                z0 += __shfl_xor_sync(0xffffffffu, z0, o);
                z1 += __shfl_xor_sync(0xffffffffu, z1, o);
            }
            float l0 = z0 + ba0, l1 = z1 + ba1;
            float a0 = 1.0f / (1.0f + expf(l1 - l0));
            float a1 = 1.0f - a0;
            F0[k] = fmaf(a0, highl, a1 * lowl) + 0.3f * (highl + lowl) + 0.1f * resl;
            F1[k] = fmaf(a0, highh, a1 * lowh) + 0.3f * (highh + lowh) + 0.1f * resh;
            F2[k] = highl;
            F3[k] = highh;
            F4[k] = lowl;
            F5[k] = lowh;
        }
        float* obl = out + ((size_t)(b * OD + dl)) * NN + n0;
        float* obh = out + ((size_t)(b * OD + dh)) * NN + n0;
        *(float4*)(obl) = make_float4(F0[0], F0[1], F0[2], F0[3]);
        *(float4*)(obh) = make_float4(F1[0], F1[1], F1[2], F1[3]);
        *(float4*)(obl + AS) = make_float4(F2[0], F2[1], F2[2], F2[3]);
        *(float4*)(obh + AS) = make_float4(F3[0], F3[1], F3[2], F3[3]);
        *(float4*)(obl + 2 * AS) = make_float4(F4[0], F4[1], F4[2], F4[3]);
        *(float4*)(obh + 2 * AS) = make_float4(F5[0], F5[1], F5[2], F5[3]);
    }
}

// ---------------- launch ------------------------------------------------------

extern "C" void kernel_launch(void* const* d_in, const int* in_sizes, int n_in, void* d_out,
                              int out_size) {
    const float* x = (const float*)d_in[0];
    const int* ei = (const int*)d_in[1];
    const int* cei = (const int*)d_in[2];
    const float* W_ht = (const float*)d_in[3];
    const float* b_ht = (const float*)d_in[4];
    const float* W_lt = (const float*)d_in[5];
    const float* b_lt = (const float*)d_in[6];
    const float* Ws_h = (const float*)d_in[7];
    const float* Wn_h = (const float*)d_in[8];
    const float* b_h = (const float*)d_in[9];
    const float* Ws_l = (const float*)d_in[10];
    const float* Wn_l = (const float*)d_in[11];
    const float* Wc_l = (const float*)d_in[12];
    const float* b_l = (const float*)d_in[13];
    const float* Whr = (const float*)d_in[14];
    const float* bhr = (const float*)d_in[15];
    const float* Wlr = (const float*)d_in[16];
    const float* blr = (const float*)d_in[17];
    const float* ghn = (const float*)d_in[18];
    const float* bhn = (const float*)d_in[19];
    const float* gln = (const float*)d_in[20];
    const float* bln = (const float*)d_in[21];
    const float* Wa = (const float*)d_in[22];
    const float* ba = (const float*)d_in[23];
    const float* Wg = (const float*)d_in[24];
    const float* bg = (const float*)d_in[25];
    const float* ggn = (const float*)d_in[26];
    const float* bgn = (const float*)d_in[27];
    float* out = (float*)d_out;

    pipeline_kernel<<<NBLK, NTHR>>>(x, ei, cei, W_ht, b_ht, W_lt, b_lt, Ws_h, Wn_h, b_h, Ws_l,
                                    Wn_l, Wc_l, b_l, Whr, bhr, Wlr, blr, Wg);
    final_kernel<<<NBLK, FW_THR>>>(out, bg, ghn, bhn, gln, bln, ggn, bgn, Wa, ba);
}

// round 5
// speedup vs baseline: 2.2436x; 1.2789x over previous
#include <cuda_runtime.h>
#include <math.h>

#define Bx 8
#define Tt 12
#define NN 10000
#define EE 160000
#define OD 64

#define NBLK 148
#define NTHR 1024
#define TTHR (NBLK * NTHR) /* 151552 */
#define CHUNK 68           /* 148*68 = 10064 >= NN */

// ---------------- scratch (__device__ globals; no allocation) ----------------
__device__ float g_xT[Bx * NN * 16];        // compact x^T [f][16] (12 used) for gather
__device__ float4 g_feat[Bx * NN * 18];     // per-node interleaved dup pairs:
                                            // [f][0..5]=x, [6..11]=aggN, [12..17]=aggC
__device__ float2 g_mflag[NN];              // {degN>0, degC>0}
__device__ int g_rowN[NN + 1];
__device__ int g_rowC[NN + 1];
__device__ int g_colN[EE];
__device__ int g_colC[EE];
__device__ int g_degN[NN];
__device__ int g_degC[NN];
__device__ int g_curN[NN];
__device__ int g_curC[NN];
__device__ int g_psumN[NBLK];
__device__ int g_psumC[NBLK];
__device__ unsigned g_cnt;  // grid-barrier counter; reset by final_kernel
// packed combined weights: 3 banks of [12][32] float4
__device__ float g_Wpk[3 * 12 * 32 * 4];
__device__ float g_bH0[OD], g_bHm[OD], g_bL0[OD], g_bLm[OD], g_bLc[OD];
// packed epilogue constants: 8 banks x 32 lanes x float4
__device__ float g_Cpk[8 * 32 * 4];

// ---------------- f32x2 helpers ----------------
#define FMA2(d, a, b) asm("fma.rn.f32x2 %0, %1, %2, %0;" : "+l"(d) : "l"(a), "l"(b))

__device__ __forceinline__ unsigned long long PK2(float lo, float hi) {
    unsigned long long r;
    asm("mov.b64 %0, {%1, %2};" : "=l"(r) : "f"(lo), "f"(hi));
    return r;
}
__device__ __forceinline__ void UPK2(float& lo, float& hi, unsigned long long v) {
    asm("mov.b64 {%0, %1}, %2;" : "=f"(lo), "=f"(hi) : "l"(v));
}

// ---------------- software grid barrier (all NBLK blocks co-resident) --------
__device__ __forceinline__ void gbar(unsigned phase) {
    __syncthreads();
    if (threadIdx.x == 0) {
        __threadfence();
        atomicAdd(&g_cnt, 1u);
        unsigned target = NBLK * phase;
        while (*(volatile unsigned*)&g_cnt < target) __nanosleep(64);
        __threadfence();
    }
    __syncthreads();
}

// ---------------- K1: persistent pipeline kernel -----------------------------
__global__ void __launch_bounds__(NTHR, 1) pipeline_kernel(
    const float* __restrict__ x, const int* __restrict__ ei, const int* __restrict__ cei,
    const float* __restrict__ W_ht, const float* __restrict__ b_ht,
    const float* __restrict__ W_lt, const float* __restrict__ b_lt,
    const float* __restrict__ Ws_h, const float* __restrict__ Wn_h,
    const float* __restrict__ b_h, const float* __restrict__ Ws_l,
    const float* __restrict__ Wn_l, const float* __restrict__ Wc_l,
    const float* __restrict__ b_l, const float* __restrict__ Whr,
    const float* __restrict__ bhr, const float* __restrict__ Wlr,
    const float* __restrict__ blr, const float* __restrict__ Wg,
    const float* __restrict__ bg, const float* __restrict__ ghn,
    const float* __restrict__ bhn, const float* __restrict__ gln,
    const float* __restrict__ bln, const float* __restrict__ ggn,
    const float* __restrict__ bgn, const float* __restrict__ Wa) {
    const int tid = threadIdx.x;
    const int bid = blockIdx.x;
    const int gtid = bid * NTHR + tid;
    __shared__ int s[256];

    // ===== Phase A: transpose x  |  count degrees (atomics)  |  prep weights
    for (int i = gtid; i < 160832; i += TTHR) {
        if (i < 80000) {
            int b = i / NN;
            int n = i - b * NN;
            float v[12];
#pragma unroll
            for (int t = 0; t < Tt; t++) v[t] = x[((size_t)b * Tt + t) * NN + n];
            float4* dst = (float4*)(g_xT + (size_t)i * 16);
            dst[0] = make_float4(v[0], v[1], v[2], v[3]);
            dst[1] = make_float4(v[4], v[5], v[6], v[7]);
            dst[2] = make_float4(v[8], v[9], v[10], v[11]);
            dst[3] = make_float4(0.f, 0.f, 0.f, 0.f);
            float4* d2 = g_feat + (size_t)i * 18;
#pragma unroll
            for (int c = 0; c < 6; c++)
                d2[c] = make_float4(v[2 * c], v[2 * c], v[2 * c + 1], v[2 * c + 1]);
        } else if (i < 160000) {
            int q = i - 80000;
            if (q < 40000) {
                int4 v = ((const int4*)(ei + EE))[q];
                atomicAdd(&g_degN[v.x], 1);
                atomicAdd(&g_degN[v.y], 1);
                atomicAdd(&g_degN[v.z], 1);
                atomicAdd(&g_degN[v.w], 1);
            } else {
                int4 v = ((const int4*)(cei + EE))[q - 40000];
                atomicAdd(&g_degC[v.x], 1);
                atomicAdd(&g_degC[v.y], 1);
                atomicAdd(&g_degC[v.z], 1);
                atomicAdd(&g_degC[v.w], 1);
            }
        } else {
            int pid = i - 160000;  // 0..831
            int t = pid >> 6;
            int d = pid & 63;
            int dl = d & 31;
            int hi = d >> 5;
            if (t < Tt) {
                float s1 = 0.f, s2 = 0.f, s3 = 0.f, s4 = 0.f, s5 = 0.f;
                for (int k = 0; k < 64; k++) {
                    float wht = W_ht[t * 64 + k];
                    float wlt = W_lt[t * 64 + k];
                    s1 += wht * (Ws_h[k * 64 + d] + 0.2f * Whr[k * 64 + d]);
                    s2 += wht * Wn_h[k * 64 + d];
                    s3 += wlt * (Ws_l[k * 64 + d] + 0.2f * Wlr[k * 64 + d]);
                    s4 += wlt * Wn_l[k * 64 + d];
                    s5 += wlt * Wc_l[k * 64 + d];
                }
                int base = (t * 32 + dl) * 4;
                g_Wpk[base + hi] = s1;
                g_Wpk[base + 2 + hi] = s2;
                g_Wpk[1536 + base + hi] = s3;
                g_Wpk[1536 + base + 2 + hi] = s4;
                g_Wpk[3072 + base + hi] = s5;
                g_Wpk[3072 + base + 2 + hi] = 2.0f * Wg[t * 64 + d];  // x_res = 2x
            } else {
                float bh0 = b_h[d] + 0.2f * bhr[d];
                float bhm = 0.f;
                float bl0 = b_l[d] + 0.2f * blr[d];
                float blm = 0.f, blc = 0.f;
                for (int k = 0; k < 64; k++) {
                    bh0 += b_ht[k] * (Ws_h[k * 64 + d] + 0.2f * Whr[k * 64 + d]);
                    bhm += b_ht[k] * Wn_h[k * 64 + d];
                    bl0 += b_lt[k] * (Ws_l[k * 64 + d] + 0.2f * Wlr[k * 64 + d]);
                    blm += b_lt[k] * Wn_l[k * 64 + d];
                    blc += b_lt[k] * Wc_l[k * 64 + d];
                }
                g_bH0[d] = bh0;
                g_bHm[d] = bhm;
                g_bL0[d] = bl0;
                g_bLm[d] = blm;
                g_bLc[d] = blc;
            }
        }
    }
    gbar(1);

    // ===== Phase B1: per-block partial sums of degrees
    {
        int base = bid * CHUNK;
        if (tid < 68)
            s[tid] = (base + tid < NN) ? g_degN[base + tid] : 0;
        else if (tid < 128)
            s[tid] = 0;
        else if (tid < 196)
            s[tid] = (base + tid - 128 < NN) ? g_degC[base + tid - 128] : 0;
        else if (tid < 256)
            s[tid] = 0;
        __syncthreads();
#pragma unroll
        for (int off = 64; off > 0; off >>= 1) {
            if (tid < off)
                s[tid] += s[tid + off];
            else if (tid >= 128 && tid < 128 + off)
                s[tid] += s[tid + off];
            __syncthreads();
        }
        if (tid == 0) g_psumN[bid] = s[0];
        if (tid == 128) g_psumC[bid] = s[128];
    }
    gbar(2);

    // ===== Phase B2: exclusive scan of 148 partials
    if (bid == 0 && tid < 64) {
        int lane = tid & 31;
        int* p = (tid < 32) ? g_psumN : g_psumC;
        int carry = 0;
        for (int k = 0; k < 5; k++) {
            int i = k * 32 + lane;
            int v = (i < NBLK) ? p[i] : 0;
            int inc = v;
#pragma unroll
            for (int o = 1; o < 32; o <<= 1) {
                int u = __shfl_up_sync(0xffffffffu, inc, o);
                if (lane >= o) inc += u;
            }
            if (i < NBLK) p[i] = carry + inc - v;
            carry += __shfl_sync(0xffffffffu, inc, 31);
        }
    }
    gbar(3);

    // ===== Phase B3: local inclusive scan -> row offsets
    {
        int base = bid * CHUNK;
        if (tid < 68)
            s[tid] = (base + tid < NN) ? g_degN[base + tid] : 0;
        else if (tid < 128)
            s[tid] = 0;
        else if (tid < 196)
            s[tid] = (base + tid - 128 < NN) ? g_degC[base + tid - 128] : 0;
        else if (tid < 256)
            s[tid] = 0;
        __syncthreads();
#pragma unroll
        for (int off = 1; off < 128; off <<= 1) {
            int v = 0;
            if (tid < 256 && (tid & 127) >= off) v = s[tid - off];
            __syncthreads();
            if (tid < 256) s[tid] += v;
            __syncthreads();
        }
        if (tid < 68) {
            int n = base + tid;
            if (n < NN) g_rowN[n + 1] = g_psumN[bid] + s[tid];
        } else if (tid >= 128 && tid < 196) {
            int n = base + tid - 128;
            if (n < NN) g_rowC[n + 1] = g_psumC[bid] + s[tid];
        }
        if (bid == 0 && tid == 0) {
            g_rowN[0] = 0;
            g_rowC[0] = 0;
        }
    }
    gbar(4);

    // ===== Phase C: fill CSR columns  |  pack epilogue constants
    for (int i = gtid; i < 2 * EE + 32; i += TTHR) {
        if (i < EE) {
            int dd = __ldg(&ei[EE + i]);
            int p = atomicAdd(&g_curN[dd], 1);
            g_colN[g_rowN[dd] + p] = __ldg(&ei[i]);
        } else if (i < 2 * EE) {
            int j = i - EE;
            int dd = __ldg(&cei[EE + j]);
            int p = atomicAdd(&g_curC[dd], 1);
            g_colC[g_rowC[dd] + p] = __ldg(&cei[j]);
        } else {
            int l = i - 2 * EE;  // 0..31
            float4* C = (float4*)g_Cpk;
            C[0 * 32 + l] = make_float4(g_bH0[l], g_bH0[l + 32], g_bHm[l], g_bHm[l + 32]);
            C[1 * 32 + l] = make_float4(g_bL0[l], g_bL0[l + 32], g_bLm[l], g_bLm[l + 32]);
            C[2 * 32 + l] = make_float4(g_bLc[l], g_bLc[l + 32], bg[l], bg[l + 32]);
            C[3 * 32 + l] = make_float4(ghn[l], ghn[l + 32], bhn[l], bhn[l + 32]);
            C[4 * 32 + l] = make_float4(gln[l], gln[l + 32], bln[l], bln[l + 32]);
            C[5 * 32 + l] = make_float4(ggn[l], ggn[l + 32], bgn[l], bgn[l + 32]);
            C[6 * 32 + l] =
                make_float4(Wa[l * 2], Wa[(l + 32) * 2], Wa[l * 2 + 1], Wa[(l + 32) * 2 + 1]);
            C[7 * 32 + l] = make_float4(Wa[(64 + l) * 2], Wa[(96 + l) * 2], Wa[(64 + l) * 2 + 1],
                                        Wa[(96 + l) * 2 + 1]);
        }
    }
    gbar(5);

    // ===== Phase D: gather-aggregate (dup pairs into g_feat) + mflag + cleanup
    for (int idx = gtid; idx < 340000; idx += TTHR) {
        if (idx < 320000) {
            int t = idx & 15;
            if (t >= Tt) continue;
            int n = idx >> 4;
            int causal = (n >= NN);
            if (causal) n -= NN;
            const int* __restrict__ row = causal ? g_rowC : g_rowN;
            const int* __restrict__ col = causal ? g_colC : g_colN;
            int rs = row[n], re = row[n + 1];
            float acc[Bx];
#pragma unroll
            for (int b = 0; b < Bx; b++) acc[b] = 0.f;
#pragma unroll 2
            for (int e = rs; e < re; e++) {
                int c = __ldg(&col[e]);
                const float* p = g_xT + c * 16 + t;
#pragma unroll
                for (int b = 0; b < Bx; b++) acc[b] += __ldg(&p[b * NN * 16]);
            }
            float invd = 1.0f / fmaxf((float)(re - rs), 1.0f);
            int off = causal ? 24 : 12;
#pragma unroll
            for (int b = 0; b < Bx; b++) {
                float v = acc[b] * invd;
                ((float2*)g_feat)[(size_t)(b * NN + n) * 36 + off + t] = make_float2(v, v);
            }
        } else if (idx < 330000) {
            int z = idx - 320000;  // zero deg/cur (int4 granularity)
            int a = z / 2500;
            int r = z - a * 2500;
            int4 zv = make_int4(0, 0, 0, 0);
            if (a == 0)
                ((int4*)g_degN)[r] = zv;
            else if (a == 1)
                ((int4*)g_degC)[r] = zv;
            else if (a == 2)
                ((int4*)g_curN)[r] = zv;
            else
                ((int4*)g_curC)[r] = zv;
        } else {
            int n = idx - 330000;  // mflag from persistent row arrays
            g_mflag[n] = make_float2((g_rowN[n + 1] > g_rowN[n]) ? 1.f : 0.f,
                                     (g_rowC[n + 1] > g_rowC[n]) ? 1.f : 0.f);
        }
    }
}

// ---------------- K2: fused epilogue -----------------------------------------
// Block = 256 thr = 8 warps; block-tile = 32 consecutive flat nodes (4/warp).
// Each thread owns dims (lane, lane+32) in f32x2; outputs staged in smem and
// flushed with lanes along n (1 L1 wavefront per store instruction).
#define FTILE 32
#define NBT (Bx * NN / FTILE) /* 2500 */
#define FBLK (NBLK * 3)       /* 444 */

__global__ void __launch_bounds__(256, 3) final_kernel(float* __restrict__ out,
                                                       const float* __restrict__ ba) {
    const int tid = threadIdx.x;
    if (blockIdx.x == 0 && tid == 0) g_cnt = 0;  // reset grid barrier for next replay
    const int lane = tid & 31;
    const int wid = tid >> 5;  // 0..7

    __shared__ ulonglong2 sW[1152];     // packed weights  (18.4 KB)
    __shared__ float4 sC[256];          // packed epilogue consts (4 KB)
    __shared__ float souts[192 * 33];   // staged outputs  (25.3 KB)

    for (int i = tid; i < 1152; i += 256) sW[i] = ((const ulonglong2*)g_Wpk)[i];
    sC[tid] = ((const float4*)g_Cpk)[tid];
    __syncthreads();

    const float ba0 = __ldg(&ba[0]), ba1 = __ldg(&ba[1]);
    const size_t AS = (size_t)Bx * OD * NN;

    for (int bt = blockIdx.x; bt < NBT; bt += FBLK) {
        const int f0 = bt * FTILE;
        const int fw = f0 + wid * 4;  // this warp's 4 flat nodes

        // ---- init accumulators (consts c0..c2 transient)
        unsigned long long hp[4], lp[4], rp[4];
        {
            float4 c0 = sC[lane], c1 = sC[32 + lane], c2 = sC[64 + lane];
#pragma unroll
            for (int k = 0; k < 4; k++) {
                int f = fw + k;
                int b = f / NN;
                int n = f - b * NN;
                float2 mf = __ldg(&g_mflag[n]);
                hp[k] = PK2(fmaf(mf.x, c0.z, c0.x), fmaf(mf.x, c0.w, c0.y));
                lp[k] = PK2(fmaf(mf.y, c2.x, fmaf(mf.x, c1.z, c1.x)),
                            fmaf(mf.y, c2.y, fmaf(mf.x, c1.w, c1.y)));
                rp[k] = PK2(c2.z, c2.w);
            }
        }
        const ulonglong2* fp = (const ulonglong2*)g_feat + (size_t)fw * 18;
#pragma unroll
        for (int c = 0; c < 6; c++) {
            ulonglong2 wA0 = sW[(2 * c) * 32 + lane];
            ulonglong2 wB0 = sW[384 + (2 * c) * 32 + lane];
            ulonglong2 wC0 = sW[768 + (2 * c) * 32 + lane];
            ulonglong2 wA1 = sW[(2 * c + 1) * 32 + lane];
            ulonglong2 wB1 = sW[384 + (2 * c + 1) * 32 + lane];
            ulonglong2 wC1 = sW[768 + (2 * c + 1) * 32 + lane];
#pragma unroll
            for (int k = 0; k < 4; k++) {
                ulonglong2 qx = __ldg(&fp[k * 18 + c]);       // {t0 pair, t1 pair}
                ulonglong2 qa = __ldg(&fp[k * 18 + 6 + c]);
                ulonglong2 qc = __ldg(&fp[k * 18 + 12 + c]);
                FMA2(hp[k], qx.x, wA0.x);
                FMA2(hp[k], qa.x, wA0.y);
                FMA2(lp[k], qx.x, wB0.x);
                FMA2(lp[k], qa.x, wB0.y);
                FMA2(lp[k], qc.x, wC0.x);
                FMA2(rp[k], qx.x, wC0.y);
                FMA2(hp[k], qx.y, wA1.x);
                FMA2(hp[k], qa.y, wA1.y);
                FMA2(lp[k], qx.y, wB1.x);
                FMA2(lp[k], qa.y, wB1.y);
                FMA2(lp[k], qc.y, wC1.x);
                FMA2(rp[k], qx.y, wC1.y);
            }
        }

        // ---- per-node epilogue (consts from smem, live only here)
        {
            float4 c3 = sC[96 + lane], c4 = sC[128 + lane], c5 = sC[160 + lane];
            float4 c6 = sC[192 + lane], c7 = sC[224 + lane];
#pragma unroll
            for (int k = 0; k < 4; k++) {
                float hl, hh, ll, lh, rl, rh;
                UPK2(hl, hh, hp[k]);
                UPK2(ll, lh, lp[k]);
                UPK2(rl, rh, rp[k]);
                float s0 = hl + hh, s1 = fmaf(hl, hl, hh * hh);
                float s2 = ll + lh, s3 = fmaf(ll, ll, lh * lh);
                float s4 = rl + rh, s5 = fmaf(rl, rl, rh * rh);
#pragma unroll
                for (int o = 16; o > 0; o >>= 1) {
                    s0 += __shfl_xor_sync(0xffffffffu, s0, o);
                    s1 += __shfl_xor_sync(0xffffffffu, s1, o);
                    s2 += __shfl_xor_sync(0xffffffffu, s2, o);
                    s3 += __shfl_xor_sync(0xffffffffu, s3, o);
                    s4 += __shfl_xor_sync(0xffffffffu, s4, o);
                    s5 += __shfl_xor_sync(0xffffffffu, s5, o);
                }
                const float inv = 1.0f / 64.0f;
                float mh = s0 * inv, vh = s1 * inv - mh * mh;
                float ml = s2 * inv, vl = s3 * inv - ml * ml;
                float mr = s4 * inv, vr = s5 * inv - mr * mr;
                float rhv = rsqrtf(vh + 1e-5f), rlv = rsqrtf(vl + 1e-5f),
                      rrv = rsqrtf(vr + 1e-5f);
                float highl = fmaf((hl - mh) * rhv, c3.x, c3.z);
                float highh = fmaf((hh - mh) * rhv, c3.y, c3.w);
                highl = (highl >= 0.f) ? highl : 0.1f * highl;
                highh = (highh >= 0.f) ? highh : 0.1f * highh;
                float lwl = fmaf((ll - ml) * rlv, c4.x, c4.z);
                float lwh = fmaf((lh - ml) * rlv, c4.y, c4.w);
                float lowl = 0.5f * lwl * (1.0f + erff(lwl * 0.70710678118654752f));
                float lowh = 0.5f * lwh * (1.0f + erff(lwh * 0.70710678118654752f));
                float resl = fmaf((rl - mr) * rrv, c5.x, c5.z);
                float resh = fmaf((rh - mr) * rrv, c5.y, c5.w);

                float z0 = highl * c6.x + highh * c6.y + lowl * c7.x + lowh * c7.y;
                float z1 = highl * c6.z + highh * c6.w + lowl * c7.z + lowh * c7.w;
#pragma unroll
                for (int o = 16; o > 0; o >>= 1) {
                    z0 += __shfl_xor_sync(0xffffffffu, z0, o);
                    z1 += __shfl_xor_sync(0xffffffffu, z1, o);
                }
                float l0 = z0 + ba0, l1 = z1 + ba1;
                float a0 = 1.0f / (1.0f + expf(l1 - l0));
                float a1 = 1.0f - a0;
                float f0v = fmaf(a0, highl, a1 * lowl) + 0.3f * (highl + lowl) + 0.1f * resl;
                float f1v = fmaf(a0, highh, a1 * lowh) + 0.3f * (highh + lowh) + 0.1f * resh;
                int j = wid * 4 + k;
                souts[(lane)*33 + j] = f0v;
                souts[(lane + 32) * 33 + j] = f1v;
                souts[(64 + lane) * 33 + j] = highl;
                souts[(96 + lane) * 33 + j] = highh;
                souts[(128 + lane) * 33 + j] = lowl;
                souts[(160 + lane) * 33 + j] = lowh;
            }
        }
        __syncthreads();
        // ---- coalesced flush: lanes along n
        {
            int b0 = f0 / NN;
            int nb = f0 - b0 * NN;
#pragma unroll
            for (int it = 0; it < 24; it++) {
                int idx = it * 256 + tid;
                int j = idx & 31;
                int row = idx >> 5;   // s*64 + d
                int ss = row >> 6;
                int d = row & 63;
                int n = nb + j, b = b0;
                if (n >= NN) {
                    n -= NN;
                    b++;
                }
                out[(size_t)ss * AS + (size_t)(b * OD + d) * NN + n] = souts[row * 33 + j];
            }
        }
        __syncthreads();
    }
}

// ---------------- launch ------------------------------------------------------

extern "C" void kernel_launch(void* const* d_in, const int* in_sizes, int n_in, void* d_out,
                              int out_size) {
    const float* x = (const float*)d_in[0];
    const int* ei = (const int*)d_in[1];
    const int* cei = (const int*)d_in[2];
    const float* W_ht = (const float*)d_in[3];
    const float* b_ht = (const float*)d_in[4];
    const float* W_lt = (const float*)d_in[5];
    const float* b_lt = (const float*)d_in[6];
    const float* Ws_h = (const float*)d_in[7];
    const float* Wn_h = (const float*)d_in[8];
    const float* b_h = (const float*)d_in[9];
    const float* Ws_l = (const float*)d_in[10];
    const float* Wn_l = (const float*)d_in[11];
    const float* Wc_l = (const float*)d_in[12];
    const float* b_l = (const float*)d_in[13];
    const float* Whr = (const float*)d_in[14];
    const float* bhr = (const float*)d_in[15];
    const float* Wlr = (const float*)d_in[16];
    const float* blr = (const float*)d_in[17];
    const float* ghn = (const float*)d_in[18];
    const float* bhn = (const float*)d_in[19];
    const float* gln = (const float*)d_in[20];
    const float* bln = (const float*)d_in[21];
    const float* Wa = (const float*)d_in[22];
    const float* ba = (const float*)d_in[23];
    const float* Wg = (const float*)d_in[24];
    const float* bg = (const float*)d_in[25];
    const float* ggn = (const float*)d_in[26];
    const float* bgn = (const float*)d_in[27];
    float* out = (float*)d_out;

    pipeline_kernel<<<NBLK, NTHR>>>(x, ei, cei, W_ht, b_ht, W_lt, b_lt, Ws_h, Wn_h, b_h, Ws_l,
                                    Wn_l, Wc_l, b_l, Whr, bhr, Wlr, blr, Wg, bg, ghn, bhn, gln,
                                    bln, ggn, bgn, Wa);
    final_kernel<<<FBLK, 256>>>(out, ba);
}

// round 6
// speedup vs baseline: 2.6377x; 1.1757x over previous
#include <cuda_runtime.h>
#include <math.h>

#define Bx 8
#define Tt 12
#define NN 10000
#define EE 160000
#define OD 64
#define FT 80000 /* flat nodes */

#define NBLK 148
#define NTHR 1024
#define TTHR (NBLK * NTHR) /* 151552 */
#define CHUNK 68           /* 148*68 = 10064 >= NN */

typedef unsigned long long ull;

// ---------------- scratch (__device__ globals; no allocation) ----------------
__device__ float g_xT[FT * 16];       // x^T [f][16] (12 used) for gather
__device__ float g_aggN[FT * 12];     // agg of x over normal edges, [f][12]
__device__ float g_aggC[FT * 12];     // agg of x over causal edges, [f][12]
__device__ float2 g_mflag[NN];        // {degN>0, degC>0}
__device__ int g_rowN[NN + 1];
__device__ int g_rowC[NN + 1];
__device__ int g_colN[EE];
__device__ int g_colC[EE];
__device__ int g_degN[NN];
__device__ int g_degC[NN];
__device__ int g_curN[NN];
__device__ int g_curC[NN];
__device__ int g_psumN[NBLK];
__device__ int g_psumC[NBLK];
__device__ unsigned g_cnt;  // grid-barrier counter; reset by final_kernel
// packed weights: 6 banks x [t:12][pair:32] of {w[d], w[d+32]} (ull = 2 floats)
// banks: 0 Ph1(x->hp) 1 Ph2(a->hp) 2 Pl1(x->lp) 3 Pl2(a->lp) 4 Pl3(c->lp) 5 Pg(x->rp)
__device__ ull g_W[6 * 12 * 32];
__device__ float g_bH0[OD], g_bHm[OD], g_bL0[OD], g_bLm[OD], g_bLc[OD];
// packed epilogue constants: 8 banks x 32 pairs x float4
__device__ float g_Cpk[8 * 32 * 4];

// ---------------- f32x2 helpers ----------------
#define FMA2(d, a, b) asm("fma.rn.f32x2 %0, %1, %2, %0;" : "+l"(d) : "l"(a), "l"(b))
#define ADD2(d, a) asm("add.rn.f32x2 %0, %0, %1;" : "+l"(d) : "l"(a))

__device__ __forceinline__ ull PK2(float lo, float hi) {
    ull r;
    asm("mov.b64 %0, {%1, %2};" : "=l"(r) : "f"(lo), "f"(hi));
    return r;
}
__device__ __forceinline__ void UPK2(float& lo, float& hi, ull v) {
    asm("mov.b64 {%0, %1}, %2;" : "=f"(lo), "=f"(hi) : "l"(v));
}

// ---------------- software grid barrier (all NBLK blocks co-resident) --------
__device__ __forceinline__ void gbar(unsigned phase) {
    __syncthreads();
    if (threadIdx.x == 0) {
        __threadfence();
        atomicAdd(&g_cnt, 1u);
        unsigned target = NBLK * phase;
        while (*(volatile unsigned*)&g_cnt < target) __nanosleep(64);
        __threadfence();
    }
    __syncthreads();
}

// ---------------- K1: persistent pipeline kernel -----------------------------
__global__ void __launch_bounds__(NTHR, 1) pipeline_kernel(
    const float* __restrict__ x, const int* __restrict__ ei, const int* __restrict__ cei,
    const float* __restrict__ W_ht, const float* __restrict__ b_ht,
    const float* __restrict__ W_lt, const float* __restrict__ b_lt,
    const float* __restrict__ Ws_h, const float* __restrict__ Wn_h,
    const float* __restrict__ b_h, const float* __restrict__ Ws_l,
    const float* __restrict__ Wn_l, const float* __restrict__ Wc_l,
    const float* __restrict__ b_l, const float* __restrict__ Whr,
    const float* __restrict__ bhr, const float* __restrict__ Wlr,
    const float* __restrict__ blr, const float* __restrict__ Wg,
    const float* __restrict__ bg, const float* __restrict__ ghn,
    const float* __restrict__ bhn, const float* __restrict__ gln,
    const float* __restrict__ bln, const float* __restrict__ ggn,
    const float* __restrict__ bgn, const float* __restrict__ Wa) {
    const int tid = threadIdx.x;
    const int bid = blockIdx.x;
    const int gtid = bid * NTHR + tid;
    __shared__ int s[256];

    // ===== Phase A: transpose x (gather layout) | count degrees | prep weights
    for (int i = gtid; i < 160832; i += TTHR) {
        if (i < 80000) {
            int b = i / NN;
            int n = i - b * NN;
            float v[12];
#pragma unroll
            for (int t = 0; t < Tt; t++) v[t] = x[((size_t)b * Tt + t) * NN + n];
            float4* dst = (float4*)(g_xT + (size_t)i * 16);
            dst[0] = make_float4(v[0], v[1], v[2], v[3]);
            dst[1] = make_float4(v[4], v[5], v[6], v[7]);
            dst[2] = make_float4(v[8], v[9], v[10], v[11]);
            dst[3] = make_float4(0.f, 0.f, 0.f, 0.f);
        } else if (i < 160000) {
            int q = i - 80000;
            if (q < 40000) {
                int4 v = ((const int4*)(ei + EE))[q];
                atomicAdd(&g_degN[v.x], 1);
                atomicAdd(&g_degN[v.y], 1);
                atomicAdd(&g_degN[v.z], 1);
                atomicAdd(&g_degN[v.w], 1);
            } else {
                int4 v = ((const int4*)(cei + EE))[q - 40000];
                atomicAdd(&g_degC[v.x], 1);
                atomicAdd(&g_degC[v.y], 1);
                atomicAdd(&g_degC[v.z], 1);
                atomicAdd(&g_degC[v.w], 1);
            }
        } else {
            int pid = i - 160000;  // 0..831
            int t = pid >> 6;
            int d = pid & 63;
            int dl = d & 31;
            int hi = d >> 5;
            if (t < Tt) {
                float s1 = 0.f, s2 = 0.f, s3 = 0.f, s4 = 0.f, s5 = 0.f;
                for (int k = 0; k < 64; k++) {
                    float wht = W_ht[t * 64 + k];
                    float wlt = W_lt[t * 64 + k];
                    s1 += wht * (Ws_h[k * 64 + d] + 0.2f * Whr[k * 64 + d]);
                    s2 += wht * Wn_h[k * 64 + d];
                    s3 += wlt * (Ws_l[k * 64 + d] + 0.2f * Wlr[k * 64 + d]);
                    s4 += wlt * Wn_l[k * 64 + d];
                    s5 += wlt * Wc_l[k * 64 + d];
                }
                float* Wf = (float*)g_W;
                int base = (t * 32 + dl) * 2 + hi;
                Wf[base] = s1;
                Wf[768 + base] = s2;
                Wf[1536 + base] = s3;
                Wf[2304 + base] = s4;
                Wf[3072 + base] = s5;
                Wf[3840 + base] = 2.0f * Wg[t * 64 + d];  // x_res = 2x
            } else {
                float bh0 = b_h[d] + 0.2f * bhr[d];
                float bhm = 0.f;
                float bl0 = b_l[d] + 0.2f * blr[d];
                float blm = 0.f, blc = 0.f;
                for (int k = 0; k < 64; k++) {
                    bh0 += b_ht[k] * (Ws_h[k * 64 + d] + 0.2f * Whr[k * 64 + d]);
                    bhm += b_ht[k] * Wn_h[k * 64 + d];
                    bl0 += b_lt[k] * (Ws_l[k * 64 + d] + 0.2f * Wlr[k * 64 + d]);
                    blm += b_lt[k] * Wn_l[k * 64 + d];
                    blc += b_lt[k] * Wc_l[k * 64 + d];
                }
                g_bH0[d] = bh0;
                g_bHm[d] = bhm;
                g_bL0[d] = bl0;
                g_bLm[d] = blm;
                g_bLc[d] = blc;
            }
        }
    }
    gbar(1);

    // ===== Phase B1: per-block partial sums of degrees
    {
        int base = bid * CHUNK;
        if (tid < 68)
            s[tid] = (base + tid < NN) ? g_degN[base + tid] : 0;
        else if (tid < 128)
            s[tid] = 0;
        else if (tid < 196)
            s[tid] = (base + tid - 128 < NN) ? g_degC[base + tid - 128] : 0;
        else if (tid < 256)
            s[tid] = 0;
        __syncthreads();
#pragma unroll
        for (int off = 64; off > 0; off >>= 1) {
            if (tid < off)
                s[tid] += s[tid + off];
            else if (tid >= 128 && tid < 128 + off)
                s[tid] += s[tid + off];
            __syncthreads();
        }
        if (tid == 0) g_psumN[bid] = s[0];
        if (tid == 128) g_psumC[bid] = s[128];
    }
    gbar(2);

    // ===== Phase B2: exclusive scan of 148 partials
    if (bid == 0 && tid < 64) {
        int lane = tid & 31;
        int* p = (tid < 32) ? g_psumN : g_psumC;
        int carry = 0;
        for (int k = 0; k < 5; k++) {
            int i = k * 32 + lane;
            int v = (i < NBLK) ? p[i] : 0;
            int inc = v;
#pragma unroll
            for (int o = 1; o < 32; o <<= 1) {
                int u = __shfl_up_sync(0xffffffffu, inc, o);
                if (lane >= o) inc += u;
            }
            if (i < NBLK) p[i] = carry + inc - v;
            carry += __shfl_sync(0xffffffffu, inc, 31);
        }
    }
    gbar(3);

    // ===== Phase B3: local inclusive scan -> row offsets
    {
        int base = bid * CHUNK;
        if (tid < 68)
            s[tid] = (base + tid < NN) ? g_degN[base + tid] : 0;
        else if (tid < 128)
            s[tid] = 0;
        else if (tid < 196)
            s[tid] = (base + tid - 128 < NN) ? g_degC[base + tid - 128] : 0;
        else if (tid < 256)
            s[tid] = 0;
        __syncthreads();
#pragma unroll
        for (int off = 1; off < 128; off <<= 1) {
            int v = 0;
            if (tid < 256 && (tid & 127) >= off) v = s[tid - off];
            __syncthreads();
            if (tid < 256) s[tid] += v;
            __syncthreads();
        }
        if (tid < 68) {
            int n = base + tid;
            if (n < NN) g_rowN[n + 1] = g_psumN[bid] + s[tid];
        } else if (tid >= 128 && tid < 196) {
            int n = base + tid - 128;
            if (n < NN) g_rowC[n + 1] = g_psumC[bid] + s[tid];
        }
        if (bid == 0 && tid == 0) {
            g_rowN[0] = 0;
            g_rowC[0] = 0;
        }
    }
    gbar(4);

    // ===== Phase C: fill CSR columns | pack epilogue constants
    for (int i = gtid; i < 2 * EE + 32; i += TTHR) {
        if (i < EE) {
            int dd = __ldg(&ei[EE + i]);
            int p = atomicAdd(&g_curN[dd], 1);
            g_colN[g_rowN[dd] + p] = __ldg(&ei[i]);
        } else if (i < 2 * EE) {
            int j = i - EE;
            int dd = __ldg(&cei[EE + j]);
            int p = atomicAdd(&g_curC[dd], 1);
            g_colC[g_rowC[dd] + p] = __ldg(&cei[j]);
        } else {
            int l = i - 2 * EE;  // 0..31
            float4* C = (float4*)g_Cpk;
            C[0 * 32 + l] = make_float4(g_bH0[l], g_bH0[l + 32], g_bHm[l], g_bHm[l + 32]);
            C[1 * 32 + l] = make_float4(g_bL0[l], g_bL0[l + 32], g_bLm[l], g_bLm[l + 32]);
            C[2 * 32 + l] = make_float4(g_bLc[l], g_bLc[l + 32], bg[l], bg[l + 32]);
            C[3 * 32 + l] = make_float4(ghn[l], ghn[l + 32], bhn[l], bhn[l + 32]);
            C[4 * 32 + l] = make_float4(gln[l], gln[l + 32], bln[l], bln[l + 32]);
            C[5 * 32 + l] = make_float4(ggn[l], ggn[l + 32], bgn[l], bgn[l + 32]);
            C[6 * 32 + l] =
                make_float4(Wa[l * 2], Wa[(l + 32) * 2], Wa[l * 2 + 1], Wa[(l + 32) * 2 + 1]);
            C[7 * 32 + l] = make_float4(Wa[(64 + l) * 2], Wa[(96 + l) * 2], Wa[(64 + l) * 2 + 1],
                                        Wa[(96 + l) * 2 + 1]);
        }
    }
    gbar(5);

    // ===== Phase D: gather-aggregate (compact [f][12]) + mflag + cleanup
    for (int idx = gtid; idx < 340000; idx += TTHR) {
        if (idx < 320000) {
            int t = idx & 15;
            if (t >= Tt) continue;
            int n = idx >> 4;
            int causal = (n >= NN);
            if (causal) n -= NN;
            const int* __restrict__ row = causal ? g_rowC : g_rowN;
            const int* __restrict__ col = causal ? g_colC : g_colN;
            float* __restrict__ dst = causal ? g_aggC : g_aggN;
            int rs = row[n], re = row[n + 1];
            float acc[Bx];
#pragma unroll
            for (int b = 0; b < Bx; b++) acc[b] = 0.f;
#pragma unroll 2
            for (int e = rs; e < re; e++) {
                int c = __ldg(&col[e]);
                const float* p = g_xT + c * 16 + t;
#pragma unroll
                for (int b = 0; b < Bx; b++) acc[b] += __ldg(&p[b * NN * 16]);
            }
            float invd = 1.0f / fmaxf((float)(re - rs), 1.0f);
#pragma unroll
            for (int b = 0; b < Bx; b++) dst[(size_t)(b * NN + n) * 12 + t] = acc[b] * invd;
        } else if (idx < 330000) {
            int z = idx - 320000;  // zero deg/cur (int4 granularity)
            int a = z / 2500;
            int r = z - a * 2500;
            int4 zv = make_int4(0, 0, 0, 0);
            if (a == 0)
                ((int4*)g_degN)[r] = zv;
            else if (a == 1)
                ((int4*)g_degC)[r] = zv;
            else if (a == 2)
                ((int4*)g_curN)[r] = zv;
            else
                ((int4*)g_curC)[r] = zv;
        } else {
            int n = idx - 330000;  // mflag from persistent row arrays
            g_mflag[n] = make_float2((g_rowN[n + 1] > g_rowN[n]) ? 1.f : 0.f,
                                     (g_rowC[n + 1] > g_rowC[n]) ? 1.f : 0.f);
        }
    }
}

// ---------------- K2: fused epilogue (thread-per-node, shuffle-free) ----------
// 256 threads/block, thread = one flat node; 96 raw f32x2 output pairs staged
// in thread-private smem columns; LN stats & softmax gate are thread-local.
#define FTILE2 256
#define NT2 ((FT + FTILE2 - 1) / FTILE2) /* 313 tiles */
// dynamic smem: sW 2304 ull | sC 512 ull (256 float4) | souts 96*256 ull
#define SM_W 2304
#define SM_C 512
#define SM_TOT ((SM_W + SM_C + 96 * FTILE2) * 8) /* 219136 B */

__device__ __forceinline__ void gemv12(ull* acc, const float* vf, const ull* wb, int p0) {
#pragma unroll
    for (int t = 0; t < Tt; t++) {
        ull q = PK2(vf[t], vf[t]);
        const ulonglong2* wp = (const ulonglong2*)(wb + t * 32 + p0);
        ulonglong2 w0 = wp[0], w1 = wp[1];
        FMA2(acc[0], q, w0.x);
        FMA2(acc[1], q, w0.y);
        FMA2(acc[2], q, w1.x);
        FMA2(acc[3], q, w1.y);
        ulonglong2 w2 = wp[2], w3 = wp[3];
        FMA2(acc[4], q, w2.x);
        FMA2(acc[5], q, w2.y);
        FMA2(acc[6], q, w3.x);
        FMA2(acc[7], q, w3.y);
    }
}

__global__ void __launch_bounds__(FTILE2, 1) final_kernel(float* __restrict__ out,
                                                          const float* __restrict__ x,
                                                          const float* __restrict__ ba) {
    const int tid = threadIdx.x;
    if (blockIdx.x == 0 && tid == 0) g_cnt = 0;  // reset grid barrier for next replay

    extern __shared__ ull sdyn[];
    ull* sW = sdyn;
    float4* sC = (float4*)(sdyn + SM_W);
    ull* souts = sdyn + SM_W + SM_C;

    for (int i = tid; i < SM_W / 2; i += FTILE2)
        ((ulonglong2*)sW)[i] = ((const ulonglong2*)g_W)[i];
    sC[tid] = ((const float4*)g_Cpk)[tid];
    __syncthreads();

    const float ba0 = __ldg(&ba[0]), ba1 = __ldg(&ba[1]);
    const size_t AS = (size_t)Bx * OD * NN;

    for (int tile = blockIdx.x; tile < NT2; tile += NBLK) {
        int f = tile * FTILE2 + tid;
        if (f >= FT) continue;  // warp-uniform except none (FT % 32 == 0)
        int b = f / NN;
        int n = f - b * NN;

        // ---- features (lane-coalesced loads)
        float vx[12], va[12], vc[12];
#pragma unroll
        for (int t = 0; t < Tt; t++) vx[t] = __ldg(&x[((size_t)b * Tt + t) * NN + n]);
        {
            const float4* pa = (const float4*)(g_aggN + (size_t)f * 12);
            const float4* pc = (const float4*)(g_aggC + (size_t)f * 12);
#pragma unroll
            for (int q4 = 0; q4 < 3; q4++) {
                float4 a4 = __ldg(&pa[q4]);
                float4 c4 = __ldg(&pc[q4]);
                va[q4 * 4] = a4.x;
                va[q4 * 4 + 1] = a4.y;
                va[q4 * 4 + 2] = a4.z;
                va[q4 * 4 + 3] = a4.w;
                vc[q4 * 4] = c4.x;
                vc[q4 * 4 + 1] = c4.y;
                vc[q4 * 4 + 2] = c4.z;
                vc[q4 * 4 + 3] = c4.w;
            }
        }
        float2 mf = __ldg(&g_mflag[n]);
        ull pkm = PK2(mf.x, mf.x), pkmc = PK2(mf.y, mf.y);

        ull sH = 0, sH2 = 0, sL = 0, sL2 = 0, sR = 0, sR2 = 0;

        // ---- hp: banks 0 (x), 1 (a); rows [0,32)
#pragma unroll
        for (int pc4 = 0; pc4 < 4; pc4++) {
            int p0 = pc4 * 8;
            ull acc[8];
#pragma unroll
            for (int j = 0; j < 8; j++) {
                float4 cb = sC[p0 + j];
                acc[j] = PK2(cb.x, cb.y);
                FMA2(acc[j], pkm, PK2(cb.z, cb.w));
            }
            gemv12(acc, vx, sW, p0);
            gemv12(acc, va, sW + 384, p0);
#pragma unroll
            for (int j = 0; j < 8; j++) {
                ADD2(sH, acc[j]);
                FMA2(sH2, acc[j], acc[j]);
                souts[(p0 + j) * FTILE2 + tid] = acc[j];
            }
        }
        // ---- lp: banks 2 (x), 3 (a), 4 (c); rows [32,64)
#pragma unroll
        for (int pc4 = 0; pc4 < 4; pc4++) {
            int p0 = pc4 * 8;
            ull acc[8];
#pragma unroll
            for (int j = 0; j < 8; j++) {
                float4 c1 = sC[32 + p0 + j];
                float4 c2 = sC[64 + p0 + j];
                acc[j] = PK2(c1.x, c1.y);
                FMA2(acc[j], pkm, PK2(c1.z, c1.w));
                FMA2(acc[j], pkmc, PK2(c2.x, c2.y));
            }
            gemv12(acc, vx, sW + 768, p0);
            gemv12(acc, va, sW + 1152, p0);
            gemv12(acc, vc, sW + 1536, p0);
#pragma unroll
            for (int j = 0; j < 8; j++) {
                ADD2(sL, acc[j]);
                FMA2(sL2, acc[j], acc[j]);
                souts[(32 + p0 + j) * FTILE2 + tid] = acc[j];
            }
        }
        // ---- rp: bank 5 (x); rows [64,96)
#pragma unroll
        for (int pc4 = 0; pc4 < 4; pc4++) {
            int p0 = pc4 * 8;
            ull acc[8];
#pragma unroll
            for (int j = 0; j < 8; j++) {
                float4 c2 = sC[64 + p0 + j];
                acc[j] = PK2(c2.z, c2.w);
            }
            gemv12(acc, vx, sW + 1920, p0);
#pragma unroll
            for (int j = 0; j < 8; j++) {
                ADD2(sR, acc[j]);
                FMA2(sR2, acc[j], acc[j]);
                souts[(64 + p0 + j) * FTILE2 + tid] = acc[j];
            }
        }

        // ---- thread-local LN stats
        const float inv = 1.0f / 64.0f;
        float u0, u1;
        UPK2(u0, u1, sH);
        float mh = (u0 + u1) * inv;
        UPK2(u0, u1, sH2);
        float vh = (u0 + u1) * inv - mh * mh;
        UPK2(u0, u1, sL);
        float ml = (u0 + u1) * inv;
        UPK2(u0, u1, sL2);
        float vl = (u0 + u1) * inv - ml * ml;
        UPK2(u0, u1, sR);
        float mr = (u0 + u1) * inv;
        UPK2(u0, u1, sR2);
        float vr = (u0 + u1) * inv - mr * mr;
        float rhv = rsqrtf(vh + 1e-5f), rlv = rsqrtf(vl + 1e-5f), rrv = rsqrtf(vr + 1e-5f);

        const size_t obase = (size_t)(b * OD) * NN + n;
        // ---- e1: LN + activations, write high/low, restage, accumulate gate
        float z0 = 0.f, z1 = 0.f;
#pragma unroll 4
        for (int i = 0; i < 32; i++) {
            ull uh = souts[i * FTILE2 + tid];
            ull ul = souts[(32 + i) * FTILE2 + tid];
            ull ur = souts[(64 + i) * FTILE2 + tid];
            float4 c3 = sC[96 + i], c4 = sC[128 + i], c5 = sC[160 + i];
            float4 c6 = sC[192 + i], c7 = sC[224 + i];
            float hl, hh, ll, lh, rl, rh;
            UPK2(hl, hh, uh);
            UPK2(ll, lh, ul);
            UPK2(rl, rh, ur);
            float highl = fmaf((hl - mh) * rhv, c3.x, c3.z);
            float highh = fmaf((hh - mh) * rhv, c3.y, c3.w);
            highl = (highl >= 0.f) ? highl : 0.1f * highl;
            highh = (highh >= 0.f) ? highh : 0.1f * highh;
            float lwl = fmaf((ll - ml) * rlv, c4.x, c4.z);
            float lwh = fmaf((lh - ml) * rlv, c4.y, c4.w);
            float lowl = 0.5f * lwl * (1.0f + erff(lwl * 0.70710678118654752f));
            float lowh = 0.5f * lwh * (1.0f + erff(lwh * 0.70710678118654752f));
            float resl = fmaf((rl - mr) * rrv, c5.x, c5.z);
            float resh = fmaf((rh - mr) * rrv, c5.y, c5.w);
            z0 += highl * c6.x + highh * c6.y + lowl * c7.x + lowh * c7.y;
            z1 += highl * c6.z + highh * c6.w + lowl * c7.z + lowh * c7.w;
            size_t base = obase + (size_t)i * NN;
            out[AS + base] = highl;
            out[AS + base + (size_t)32 * NN] = highh;
            out[2 * AS + base] = lowl;
            out[2 * AS + base + (size_t)32 * NN] = lowh;
            souts[i * FTILE2 + tid] = PK2(highl, highh);
            souts[(32 + i) * FTILE2 + tid] = PK2(lowl, lowh);
            souts[(64 + i) * FTILE2 + tid] = PK2(resl, resh);
        }
        float a0 = 1.0f / (1.0f + expf((z1 + ba1) - (z0 + ba0)));
        float a1 = 1.0f - a0;
        // ---- e2: fused output
#pragma unroll 4
        for (int i = 0; i < 32; i++) {
            float hl, hh, ll, lh, rl, rh;
            UPK2(hl, hh, souts[i * FTILE2 + tid]);
            UPK2(ll, lh, souts[(32 + i) * FTILE2 + tid]);
            UPK2(rl, rh, souts[(64 + i) * FTILE2 + tid]);
            float fl = fmaf(a0, hl, a1 * ll) + 0.3f * (hl + ll) + 0.1f * rl;
            float fh = fmaf(a0, hh, a1 * lh) + 0.3f * (hh + lh) + 0.1f * rh;
            size_t base = obase + (size_t)i * NN;
            out[base] = fl;
            out[base + (size_t)32 * NN] = fh;
        }
    }
}

// ---------------- launch ------------------------------------------------------

extern "C" void kernel_launch(void* const* d_in, const int* in_sizes, int n_in, void* d_out,
                              int out_size) {
    const float* x = (const float*)d_in[0];
    const int* ei = (const int*)d_in[1];
    const int* cei = (const int*)d_in[2];
    const float* W_ht = (const float*)d_in[3];
    const float* b_ht = (const float*)d_in[4];
    const float* W_lt = (const float*)d_in[5];
    const float* b_lt = (const float*)d_in[6];
    const float* Ws_h = (const float*)d_in[7];
    const float* Wn_h = (const float*)d_in[8];
    const float* b_h = (const float*)d_in[9];
    const float* Ws_l = (const float*)d_in[10];
    const float* Wn_l = (const float*)d_in[11];
    const float* Wc_l = (const float*)d_in[12];
    const float* b_l = (const float*)d_in[13];
    const float* Whr = (const float*)d_in[14];
    const float* bhr = (const float*)d_in[15];
    const float* Wlr = (const float*)d_in[16];
    const float* blr = (const float*)d_in[17];
    const float* ghn = (const float*)d_in[18];
    const float* bhn = (const float*)d_in[19];
    const float* gln = (const float*)d_in[20];
    const float* bln = (const float*)d_in[21];
    const float* Wa = (const float*)d_in[22];
    const float* ba = (const float*)d_in[23];
    const float* Wg = (const float*)d_in[24];
    const float* bg = (const float*)d_in[25];
    const float* ggn = (const float*)d_in[26];
    const float* bgn = (const float*)d_in[27];
    float* out = (float*)d_out;

    cudaFuncSetAttribute(final_kernel, cudaFuncAttributeMaxDynamicSharedMemorySize, SM_TOT);

    pipeline_kernel<<<NBLK, NTHR>>>(x, ei, cei, W_ht, b_ht, W_lt, b_lt, Ws_h, Wn_h, b_h, Ws_l,
                                    Wn_l, Wc_l, b_l, Whr, bhr, Wlr, blr, Wg, bg, ghn, bhn, gln,
                                    bln, ggn, bgn, Wa);
    final_kernel<<<NBLK, FTILE2, SM_TOT>>>(out, x, ba);
}